// round 1
// baseline (speedup 1.0000x reference)
#include <cuda_runtime.h>
#include <math.h>

#define TOK   8192
#define DM    384
#define DI    768
#define NST   16
#define FFNDIM 1024
#define LSEQ  2048

// ---------------- scratch (static device globals; no allocs) ----------------
__device__ float g_h[TOK * DM];
__device__ float g_xz[TOK * 2 * DI];
__device__ float g_xconv[TOK * DI];
__device__ float g_delta[TOK * DI];
__device__ float g_bc[TOK * 2 * NST];
__device__ float g_y[TOK * DI];
__device__ float g_mm[TOK * DM];
__device__ float g_x1[TOK * DM];
__device__ float g_gate[TOK * FFNDIM];
__device__ float g_up[TOK * FFNDIM];

__device__ __forceinline__ float siluf(float x) { return x / (1.f + __expf(-x)); }

// ---------------- RMSNorm: one block per token, 128 threads ----------------
__global__ void rmsnorm_k(const float* __restrict__ x, const float* __restrict__ w,
                          float* __restrict__ o) {
    int t = blockIdx.x, tid = threadIdx.x;
    const float* xr = x + (size_t)t * DM;
    float v0 = xr[tid], v1 = xr[tid + 128], v2 = xr[tid + 256];
    float ss = v0 * v0 + v1 * v1 + v2 * v2;
    #pragma unroll
    for (int s = 16; s > 0; s >>= 1) ss += __shfl_xor_sync(0xffffffffu, ss, s);
    __shared__ float sm[4];
    if ((tid & 31) == 0) sm[tid >> 5] = ss;
    __syncthreads();
    float tot = sm[0] + sm[1] + sm[2] + sm[3];
    float sc = rsqrtf(tot / (float)DM + 1e-6f);
    float* orow = o + (size_t)t * DM;
    orow[tid]       = v0 * sc * w[tid];
    orow[tid + 128] = v1 * sc * w[tid + 128];
    orow[tid + 256] = v2 * sc * w[tid + 256];
}

// ------------- LayerNorm(mm)*gamma+beta + residual -> o -------------
__global__ void lnres_k(const float* __restrict__ mm, const float* __restrict__ res,
                        const float* __restrict__ gamma, const float* __restrict__ beta,
                        float* __restrict__ o) {
    int t = blockIdx.x, tid = threadIdx.x;
    const float* r_ = mm + (size_t)t * DM;
    float v0 = r_[tid], v1 = r_[tid + 128], v2 = r_[tid + 256];
    float s = v0 + v1 + v2;
    float ss = v0 * v0 + v1 * v1 + v2 * v2;
    #pragma unroll
    for (int k = 16; k > 0; k >>= 1) {
        s  += __shfl_xor_sync(0xffffffffu, s, k);
        ss += __shfl_xor_sync(0xffffffffu, ss, k);
    }
    __shared__ float sm1[4], sm2[4];
    if ((tid & 31) == 0) { sm1[tid >> 5] = s; sm2[tid >> 5] = ss; }
    __syncthreads();
    s  = sm1[0] + sm1[1] + sm1[2] + sm1[3];
    ss = sm2[0] + sm2[1] + sm2[2] + sm2[3];
    float mu  = s / (float)DM;
    float var = ss / (float)DM - mu * mu;
    float rs  = rsqrtf(var + 1e-5f);
    const float* rr = res + (size_t)t * DM;
    float* orow = o + (size_t)t * DM;
    orow[tid]       = rr[tid]       + (v0 - mu) * rs * gamma[tid]       + beta[tid];
    orow[tid + 128] = rr[tid + 128] + (v1 - mu) * rs * gamma[tid + 128] + beta[tid + 128];
    orow[tid + 256] = rr[tid + 256] + (v2 - mu) * rs * gamma[tid + 256] + beta[tid + 256];
}

// ---------------- generic SGEMM: C[M,N] = A[M,K] @ B[K,N] ----------------
// BM=BN=128, BK=16, 256 threads, 8x8 per thread.
// EPI: 0 = store, 1 = +bias, 3 = +bias then softplus, 4 = +res (same layout as C)
template <int EPI>
__global__ void __launch_bounds__(256, 2) sgemm_k(
    const float* __restrict__ A, int lda,
    const float* __restrict__ B, int ldb,
    float* __restrict__ C, int ldc,
    int M, int N, int K,
    const float* __restrict__ bias,
    const float* __restrict__ res) {
    __shared__ float As[16][128];
    __shared__ float Bs[16][128];
    int tid = threadIdx.x;
    int m0 = blockIdx.y * 128, n0 = blockIdx.x * 128;
    float acc[8][8] = {};
    int arow = tid >> 2, acol = (tid & 3) * 4;
    int brow = tid >> 5, bcol = (tid & 31) * 4;
    int ms = (tid >> 4) * 8, ns = (tid & 15) * 8;

    for (int k0 = 0; k0 < K; k0 += 16) {
        #pragma unroll
        for (int i = 0; i < 2; i++) {
            int r = arow + i * 64;
            float4 v = *(const float4*)(A + (size_t)(m0 + r) * lda + k0 + acol);
            As[acol + 0][r] = v.x; As[acol + 1][r] = v.y;
            As[acol + 2][r] = v.z; As[acol + 3][r] = v.w;
        }
        #pragma unroll
        for (int i = 0; i < 2; i++) {
            int r = brow + i * 8;
            int c = n0 + bcol;
            float4 v = make_float4(0.f, 0.f, 0.f, 0.f);
            if (c < N) v = *(const float4*)(B + (size_t)(k0 + r) * ldb + c);
            *(float4*)&Bs[r][bcol] = v;
        }
        __syncthreads();
        #pragma unroll
        for (int k = 0; k < 16; k++) {
            float a[8], b[8];
            *(float4*)&a[0] = *(const float4*)&As[k][ms];
            *(float4*)&a[4] = *(const float4*)&As[k][ms + 4];
            *(float4*)&b[0] = *(const float4*)&Bs[k][ns];
            *(float4*)&b[4] = *(const float4*)&Bs[k][ns + 4];
            #pragma unroll
            for (int i = 0; i < 8; i++)
                #pragma unroll
                for (int j = 0; j < 8; j++) acc[i][j] = fmaf(a[i], b[j], acc[i][j]);
        }
        __syncthreads();
    }
    #pragma unroll
    for (int i = 0; i < 8; i++) {
        int row = m0 + ms + i;
        #pragma unroll
        for (int j4 = 0; j4 < 8; j4 += 4) {
            int c = n0 + ns + j4;
            if (c < N) {
                float4 v;
                float* pv = &v.x;
                #pragma unroll
                for (int j = 0; j < 4; j++) {
                    float tv = acc[i][j4 + j];
                    if (EPI == 1 || EPI == 3) tv += bias[c + j];
                    if (EPI == 3) tv = (tv > 20.f) ? tv : log1pf(__expf(tv));
                    if (EPI == 4) tv += res[(size_t)row * ldc + c + j];
                    pv[j] = tv;
                }
                *(float4*)(C + (size_t)row * ldc + c) = v;
            }
        }
    }
}

// -------- conv1d (k=4, SAME pad (1,2), full 768->768) as implicit-im2col GEMM ------
// out[t,o] = silu( bias[o] + sum_w sum_i x_inner[tok_shift(t,w), i] * W[w,i,o] )
// x_inner = first DI cols of xz (row stride 2*DI).
__global__ void __launch_bounds__(256, 2) conv_k(
    const float* __restrict__ xz, const float* __restrict__ W,
    const float* __restrict__ bias, float* __restrict__ out) {
    __shared__ float As[16][128];
    __shared__ float Bs[16][128];
    int tid = threadIdx.x;
    int m0 = blockIdx.y * 128, n0 = blockIdx.x * 128;
    float acc[8][8] = {};
    int arow = tid >> 2, acol = (tid & 3) * 4;
    int brow = tid >> 5, bcol = (tid & 31) * 4;
    int ms = (tid >> 4) * 8, ns = (tid & 15) * 8;

    for (int w = 0; w < 4; w++) {
        for (int k0 = 0; k0 < DI; k0 += 16) {
            #pragma unroll
            for (int i = 0; i < 2; i++) {
                int r = arow + i * 64;
                int tok = m0 + r;
                int l = tok & (LSEQ - 1);
                int ls = l + w - 1;
                float4 v = make_float4(0.f, 0.f, 0.f, 0.f);
                if ((unsigned)ls < LSEQ)
                    v = *(const float4*)(xz + (size_t)((tok - l) + ls) * (2 * DI) + k0 + acol);
                As[acol + 0][r] = v.x; As[acol + 1][r] = v.y;
                As[acol + 2][r] = v.z; As[acol + 3][r] = v.w;
            }
            #pragma unroll
            for (int i = 0; i < 2; i++) {
                int r = brow + i * 8;
                *(float4*)&Bs[r][bcol] =
                    *(const float4*)(W + (size_t)(w * DI + k0 + r) * DI + n0 + bcol);
            }
            __syncthreads();
            #pragma unroll
            for (int k = 0; k < 16; k++) {
                float a[8], b[8];
                *(float4*)&a[0] = *(const float4*)&As[k][ms];
                *(float4*)&a[4] = *(const float4*)&As[k][ms + 4];
                *(float4*)&b[0] = *(const float4*)&Bs[k][ns];
                *(float4*)&b[4] = *(const float4*)&Bs[k][ns + 4];
                #pragma unroll
                for (int i = 0; i < 8; i++)
                    #pragma unroll
                    for (int j = 0; j < 8; j++) acc[i][j] = fmaf(a[i], b[j], acc[i][j]);
            }
            __syncthreads();
        }
    }
    #pragma unroll
    for (int i = 0; i < 8; i++) {
        int row = m0 + ms + i;
        #pragma unroll
        for (int j4 = 0; j4 < 8; j4 += 4) {
            int c = n0 + ns + j4;
            float4 v;
            float* pv = &v.x;
            #pragma unroll
            for (int j = 0; j < 4; j++) pv[j] = siluf(acc[i][j4 + j] + bias[c + j]);
            *(float4*)(out + (size_t)row * DI + c) = v;
        }
    }
}

// ---------------- selective scan ----------------
// 16 lanes (states) per (b,d) channel; 2 channels per warp; 8 channels per block.
// delta has softplus pre-applied (dt_proj epilogue).
__global__ void scan_k(const float* __restrict__ xc, const float* __restrict__ dl,
                       const float* __restrict__ bc, const float* __restrict__ xz,
                       const float* __restrict__ A_log, const float* __restrict__ Dp,
                       float* __restrict__ y) {
    int tid = threadIdx.x;
    int pair = blockIdx.x * 8 + (tid >> 4);
    int n = tid & 15;
    int b = pair / DI;
    int d = pair - b * DI;
    float a = -__expf(A_log[d * NST + n]);
    float Dv = Dp[d];
    float hs = 0.f;
    size_t base = (size_t)b * LSEQ;
    #pragma unroll 4
    for (int l = 0; l < LSEQ; l++) {
        size_t t = base + l;
        float xv = xc[t * DI + d];
        float de = dl[t * DI + d];
        float Bv = bc[t * 32 + n];
        float Cv = bc[t * 32 + 16 + n];
        hs = __expf(de * a) * hs + de * Bv * xv;
        float yv = hs * Cv;
        yv += __shfl_xor_sync(0xffffffffu, yv, 8);
        yv += __shfl_xor_sync(0xffffffffu, yv, 4);
        yv += __shfl_xor_sync(0xffffffffu, yv, 2);
        yv += __shfl_xor_sync(0xffffffffu, yv, 1);
        if (n == 0) {
            float z = xz[t * (2 * DI) + DI + d];
            y[t * DI + d] = (yv + Dv * xv) * siluf(z);
        }
    }
}

// ---------------- SwiGLU elementwise: g = silu(g) * u ----------------
__global__ void swiglu_k(float* __restrict__ g, const float* __restrict__ u, int n) {
    int i = blockIdx.x * blockDim.x + threadIdx.x;
    if (i < n) {
        float gv = g[i];
        g[i] = siluf(gv) * u[i];
    }
}

// ---------------- launch ----------------
extern "C" void kernel_launch(void* const* d_in, const int* in_sizes, int n_in,
                              void* d_out, int out_size) {
    const float* x         = (const float*)d_in[0];
    const float* rms1_w    = (const float*)d_in[1];
    const float* rms2_w    = (const float*)d_in[2];
    const float* in_proj_w = (const float*)d_in[3];
    const float* conv_w    = (const float*)d_in[4];
    const float* conv_b    = (const float*)d_in[5];
    const float* x_proj_w  = (const float*)d_in[6];
    const float* dt_proj_w = (const float*)d_in[7];
    const float* dt_proj_b = (const float*)d_in[8];
    const float* A_log     = (const float*)d_in[9];
    const float* D_param   = (const float*)d_in[10];
    const float* out_proj_w= (const float*)d_in[11];
    const float* ln_gamma  = (const float*)d_in[12];
    const float* ln_beta   = (const float*)d_in[13];
    const float* gate_w    = (const float*)d_in[14];
    const float* up_w      = (const float*)d_in[15];
    const float* down_w    = (const float*)d_in[16];
    float* out = (float*)d_out;

    float *h, *xz, *xc, *de, *bc, *y, *mm, *x1, *ga, *up;
    cudaGetSymbolAddress((void**)&h,  g_h);
    cudaGetSymbolAddress((void**)&xz, g_xz);
    cudaGetSymbolAddress((void**)&xc, g_xconv);
    cudaGetSymbolAddress((void**)&de, g_delta);
    cudaGetSymbolAddress((void**)&bc, g_bc);
    cudaGetSymbolAddress((void**)&y,  g_y);
    cudaGetSymbolAddress((void**)&mm, g_mm);
    cudaGetSymbolAddress((void**)&x1, g_x1);
    cudaGetSymbolAddress((void**)&ga, g_gate);
    cudaGetSymbolAddress((void**)&up, g_up);

    // 1. rms1
    rmsnorm_k<<<TOK, 128>>>(x, rms1_w, h);
    // 2. in_proj: [8192,384]@[384,1536]
    sgemm_k<0><<<dim3(12, 64), 256>>>(h, DM, in_proj_w, 2 * DI, xz, 2 * DI,
                                      TOK, 2 * DI, DM, nullptr, nullptr);
    // 3. conv1d + bias + silu
    conv_k<<<dim3(6, 64), 256>>>(xz, conv_w, conv_b, xc);
    // 4. x_proj: [8192,768]@[768,32] -> B,C
    sgemm_k<0><<<dim3(1, 64), 256>>>(xc, DI, x_proj_w, 32, bc, 32,
                                     TOK, 32, DI, nullptr, nullptr);
    // 5. dt_proj + bias + softplus
    sgemm_k<3><<<dim3(6, 64), 256>>>(xc, DI, dt_proj_w, DI, de, DI,
                                     TOK, DI, DI, dt_proj_b, nullptr);
    // 6. selective scan (+ D*x, * silu(z))
    scan_k<<<(4 * DI) / 8, 128>>>(xc, de, bc, xz, A_log, D_param, y);
    // 7. out_proj
    sgemm_k<0><<<dim3(3, 64), 256>>>(y, DI, out_proj_w, DM, mm, DM,
                                     TOK, DM, DI, nullptr, nullptr);
    // 8. layer_norm + residual -> x1
    lnres_k<<<TOK, 128>>>(mm, x, ln_gamma, ln_beta, x1);
    // 9. rms2
    rmsnorm_k<<<TOK, 128>>>(x1, rms2_w, h);
    // 10/11. gate & up
    sgemm_k<0><<<dim3(8, 64), 256>>>(h, DM, gate_w, FFNDIM, ga, FFNDIM,
                                     TOK, FFNDIM, DM, nullptr, nullptr);
    sgemm_k<0><<<dim3(8, 64), 256>>>(h, DM, up_w, FFNDIM, up, FFNDIM,
                                     TOK, FFNDIM, DM, nullptr, nullptr);
    // 12. silu(gate)*up
    swiglu_k<<<(TOK * FFNDIM + 255) / 256, 256>>>(ga, up, TOK * FFNDIM);
    // 13. down proj + residual -> out
    sgemm_k<4><<<dim3(3, 64), 256>>>(ga, FFNDIM, down_w, DM, out, DM,
                                     TOK, DM, FFNDIM, nullptr, x1);
}

// round 2
// speedup vs baseline: 1.1352x; 1.1352x over previous
#include <cuda_runtime.h>
#include <math.h>
#include <stdint.h>

#define TOK   8192
#define DM    384
#define DI    768
#define NST   16
#define FFNDIM 1024
#define LSEQ  2048

#define PADA 20
#define PADB 136

// ---------------- scratch (static device globals; no allocs) ----------------
__device__ float g_h[TOK * DM];
__device__ float g_xz[TOK * 2 * DI];
__device__ float g_xconv[TOK * DI];
__device__ float g_delta[TOK * DI];
__device__ float g_bc[TOK * 2 * NST];
__device__ float g_y[TOK * DI];
__device__ float g_mm[TOK * DM];
__device__ float g_x1[TOK * DM];
__device__ float g_gate[TOK * FFNDIM];
__device__ float g_up[TOK * FFNDIM];

__device__ __forceinline__ float siluf(float x) { return x / (1.f + __expf(-x)); }

__device__ __forceinline__ uint32_t f2tf(float f) {
    uint32_t r;
    asm("cvt.rna.tf32.f32 %0, %1;" : "=r"(r) : "f"(f));
    return r;
}

#define MMA_TF32(d, a, b)                                                    \
    asm volatile(                                                            \
        "mma.sync.aligned.m16n8k8.row.col.f32.tf32.tf32.f32 "                \
        "{%0,%1,%2,%3},{%4,%5,%6,%7},{%8,%9},{%0,%1,%2,%3};\n"               \
        : "+f"((d)[0]), "+f"((d)[1]), "+f"((d)[2]), "+f"((d)[3])             \
        : "r"((a)[0]), "r"((a)[1]), "r"((a)[2]), "r"((a)[3]),                \
          "r"((b)[0]), "r"((b)[1]))

// ---------------- RMSNorm ----------------
__global__ void rmsnorm_k(const float* __restrict__ x, const float* __restrict__ w,
                          float* __restrict__ o) {
    int t = blockIdx.x, tid = threadIdx.x;
    const float* xr = x + (size_t)t * DM;
    float v0 = xr[tid], v1 = xr[tid + 128], v2 = xr[tid + 256];
    float ss = v0 * v0 + v1 * v1 + v2 * v2;
    #pragma unroll
    for (int s = 16; s > 0; s >>= 1) ss += __shfl_xor_sync(0xffffffffu, ss, s);
    __shared__ float sm[4];
    if ((tid & 31) == 0) sm[tid >> 5] = ss;
    __syncthreads();
    float tot = sm[0] + sm[1] + sm[2] + sm[3];
    float sc = rsqrtf(tot / (float)DM + 1e-6f);
    float* orow = o + (size_t)t * DM;
    orow[tid]       = v0 * sc * w[tid];
    orow[tid + 128] = v1 * sc * w[tid + 128];
    orow[tid + 256] = v2 * sc * w[tid + 256];
}

// ------------- LayerNorm(mm)*gamma+beta + residual -> o -------------
__global__ void lnres_k(const float* __restrict__ mm, const float* __restrict__ res,
                        const float* __restrict__ gamma, const float* __restrict__ beta,
                        float* __restrict__ o) {
    int t = blockIdx.x, tid = threadIdx.x;
    const float* r_ = mm + (size_t)t * DM;
    float v0 = r_[tid], v1 = r_[tid + 128], v2 = r_[tid + 256];
    float s = v0 + v1 + v2;
    float ss = v0 * v0 + v1 * v1 + v2 * v2;
    #pragma unroll
    for (int k = 16; k > 0; k >>= 1) {
        s  += __shfl_xor_sync(0xffffffffu, s, k);
        ss += __shfl_xor_sync(0xffffffffu, ss, k);
    }
    __shared__ float sm1[4], sm2[4];
    if ((tid & 31) == 0) { sm1[tid >> 5] = s; sm2[tid >> 5] = ss; }
    __syncthreads();
    s  = sm1[0] + sm1[1] + sm1[2] + sm1[3];
    ss = sm2[0] + sm2[1] + sm2[2] + sm2[3];
    float mu  = s / (float)DM;
    float var = ss / (float)DM - mu * mu;
    float rs  = rsqrtf(var + 1e-5f);
    const float* rr = res + (size_t)t * DM;
    float* orow = o + (size_t)t * DM;
    orow[tid]       = rr[tid]       + (v0 - mu) * rs * gamma[tid]       + beta[tid];
    orow[tid + 128] = rr[tid + 128] + (v1 - mu) * rs * gamma[tid + 128] + beta[tid + 128];
    orow[tid + 256] = rr[tid + 256] + (v2 - mu) * rs * gamma[tid + 256] + beta[tid + 256];
}

// ---------------- TF32 tensor-core GEMM: C[M,N] = A[M,K] @ B[K,N] --------------
// BM=128, BN=128, BK=16, 256 threads = 8 warps (2x4), warp tile 64x32.
// EPI: 0 = store, 3 = +bias then softplus, 4 = +res
template <int EPI>
__global__ void __launch_bounds__(256, 2) tgemm_k(
    const float* __restrict__ A, int lda,
    const float* __restrict__ B, int ldb,
    float* __restrict__ C, int ldc,
    int M, int N, int K,
    const float* __restrict__ bias,
    const float* __restrict__ res) {
    __shared__ uint32_t As[128 * PADA];
    __shared__ uint32_t Bs[16 * PADB];
    int tid = threadIdx.x, lane = tid & 31, wid = tid >> 5;
    int wm = wid >> 2, wn = wid & 3;
    int m0 = blockIdx.y * 128, n0 = blockIdx.x * 128;
    float acc[4][4][4] = {};
    int ar = tid >> 1, ak = (tid & 1) * 8;
    int bk = tid >> 5, bn = (tid & 31) * 4;
    int lr = lane >> 2, lc = lane & 3;

    for (int k0 = 0; k0 < K; k0 += 16) {
        // A tile -> As[m][k] (pad 20)
        {
            const float* ap = A + (size_t)(m0 + ar) * lda + k0 + ak;
            float4 v0 = *(const float4*)ap;
            float4 v1 = *(const float4*)(ap + 4);
            uint4 u0 = make_uint4(f2tf(v0.x), f2tf(v0.y), f2tf(v0.z), f2tf(v0.w));
            uint4 u1 = make_uint4(f2tf(v1.x), f2tf(v1.y), f2tf(v1.z), f2tf(v1.w));
            *(uint4*)&As[ar * PADA + ak]     = u0;
            *(uint4*)&As[ar * PADA + ak + 4] = u1;
        }
        // B tile -> Bs[k][n] (pad 136)
        #pragma unroll
        for (int i = 0; i < 2; i++) {
            int kr = bk + i * 8;
            int c = n0 + bn;
            float4 v = make_float4(0.f, 0.f, 0.f, 0.f);
            if (c < N) v = *(const float4*)(B + (size_t)(k0 + kr) * ldb + c);
            uint4 u = make_uint4(f2tf(v.x), f2tf(v.y), f2tf(v.z), f2tf(v.w));
            *(uint4*)&Bs[kr * PADB + bn] = u;
        }
        __syncthreads();
        #pragma unroll
        for (int ks = 0; ks < 2; ks++) {
            uint32_t af[4][4], bf[4][2];
            #pragma unroll
            for (int mt = 0; mt < 4; mt++) {
                int R = wm * 64 + mt * 16;
                af[mt][0] = As[(R + lr) * PADA + ks * 8 + lc];
                af[mt][1] = As[(R + lr + 8) * PADA + ks * 8 + lc];
                af[mt][2] = As[(R + lr) * PADA + ks * 8 + 4 + lc];
                af[mt][3] = As[(R + lr + 8) * PADA + ks * 8 + 4 + lc];
            }
            #pragma unroll
            for (int nt = 0; nt < 4; nt++) {
                int CB = wn * 32 + nt * 8;
                bf[nt][0] = Bs[(ks * 8 + lc) * PADB + CB + lr];
                bf[nt][1] = Bs[(ks * 8 + 4 + lc) * PADB + CB + lr];
            }
            #pragma unroll
            for (int mt = 0; mt < 4; mt++)
                #pragma unroll
                for (int nt = 0; nt < 4; nt++) MMA_TF32(acc[mt][nt], af[mt], bf[nt]);
        }
        __syncthreads();
    }
    // epilogue
    int c2 = lc * 2;
    #pragma unroll
    for (int mt = 0; mt < 4; mt++) {
        int row0 = m0 + wm * 64 + mt * 16 + lr;
        #pragma unroll
        for (int nt = 0; nt < 4; nt++) {
            int col = n0 + wn * 32 + nt * 8 + c2;
            if (col < N) {
                #pragma unroll
                for (int h = 0; h < 2; h++) {
                    int row = row0 + h * 8;
                    float e0 = acc[mt][nt][h * 2 + 0];
                    float e1 = acc[mt][nt][h * 2 + 1];
                    if (EPI == 3) {
                        e0 += bias[col];     e1 += bias[col + 1];
                        e0 = (e0 > 20.f) ? e0 : log1pf(__expf(e0));
                        e1 = (e1 > 20.f) ? e1 : log1pf(__expf(e1));
                    }
                    if (EPI == 4) {
                        e0 += res[(size_t)row * ldc + col];
                        e1 += res[(size_t)row * ldc + col + 1];
                    }
                    *(float2*)(C + (size_t)row * ldc + col) = make_float2(e0, e1);
                }
            }
        }
    }
}

// -------- conv1d (k=4, SAME pad (1,2), 768->768) as implicit-im2col TF32 GEMM ------
__global__ void __launch_bounds__(256, 2) tconv_k(
    const float* __restrict__ xz, const float* __restrict__ W,
    const float* __restrict__ bias, float* __restrict__ out) {
    __shared__ uint32_t As[128 * PADA];
    __shared__ uint32_t Bs[16 * PADB];
    int tid = threadIdx.x, lane = tid & 31, wid = tid >> 5;
    int wm = wid >> 2, wn = wid & 3;
    int m0 = blockIdx.y * 128, n0 = blockIdx.x * 128;
    float acc[4][4][4] = {};
    int ar = tid >> 1, ak = (tid & 1) * 8;
    int bk = tid >> 5, bn = (tid & 31) * 4;
    int lr = lane >> 2, lc = lane & 3;

    int tok = m0 + ar;
    int l = tok & (LSEQ - 1);
    int tb = tok - l;

    for (int w = 0; w < 4; w++) {
        int ls = l + w - 1;
        bool valid = (unsigned)ls < LSEQ;
        const float* arow = xz + (size_t)(tb + ls) * (2 * DI);
        for (int k0 = 0; k0 < DI; k0 += 16) {
            {
                float4 v0 = make_float4(0.f, 0.f, 0.f, 0.f), v1 = v0;
                if (valid) {
                    v0 = *(const float4*)(arow + k0 + ak);
                    v1 = *(const float4*)(arow + k0 + ak + 4);
                }
                uint4 u0 = make_uint4(f2tf(v0.x), f2tf(v0.y), f2tf(v0.z), f2tf(v0.w));
                uint4 u1 = make_uint4(f2tf(v1.x), f2tf(v1.y), f2tf(v1.z), f2tf(v1.w));
                *(uint4*)&As[ar * PADA + ak]     = u0;
                *(uint4*)&As[ar * PADA + ak + 4] = u1;
            }
            #pragma unroll
            for (int i = 0; i < 2; i++) {
                int kr = bk + i * 8;
                float4 v = *(const float4*)(W + (size_t)(w * DI + k0 + kr) * DI + n0 + bn);
                uint4 u = make_uint4(f2tf(v.x), f2tf(v.y), f2tf(v.z), f2tf(v.w));
                *(uint4*)&Bs[kr * PADB + bn] = u;
            }
            __syncthreads();
            #pragma unroll
            for (int ks = 0; ks < 2; ks++) {
                uint32_t af[4][4], bf[4][2];
                #pragma unroll
                for (int mt = 0; mt < 4; mt++) {
                    int R = wm * 64 + mt * 16;
                    af[mt][0] = As[(R + lr) * PADA + ks * 8 + lc];
                    af[mt][1] = As[(R + lr + 8) * PADA + ks * 8 + lc];
                    af[mt][2] = As[(R + lr) * PADA + ks * 8 + 4 + lc];
                    af[mt][3] = As[(R + lr + 8) * PADA + ks * 8 + 4 + lc];
                }
                #pragma unroll
                for (int nt = 0; nt < 4; nt++) {
                    int CB = wn * 32 + nt * 8;
                    bf[nt][0] = Bs[(ks * 8 + lc) * PADB + CB + lr];
                    bf[nt][1] = Bs[(ks * 8 + 4 + lc) * PADB + CB + lr];
                }
                #pragma unroll
                for (int mt = 0; mt < 4; mt++)
                    #pragma unroll
                    for (int nt = 0; nt < 4; nt++) MMA_TF32(acc[mt][nt], af[mt], bf[nt]);
            }
            __syncthreads();
        }
    }
    int c2 = lc * 2;
    #pragma unroll
    for (int mt = 0; mt < 4; mt++) {
        int row0 = m0 + wm * 64 + mt * 16 + lr;
        #pragma unroll
        for (int nt = 0; nt < 4; nt++) {
            int col = n0 + wn * 32 + nt * 8 + c2;
            #pragma unroll
            for (int h = 0; h < 2; h++) {
                int row = row0 + h * 8;
                float e0 = siluf(acc[mt][nt][h * 2 + 0] + bias[col]);
                float e1 = siluf(acc[mt][nt][h * 2 + 1] + bias[col + 1]);
                *(float2*)(out + (size_t)row * DI + col) = make_float2(e0, e1);
            }
        }
    }
}

// ---------------- selective scan ----------------
__global__ void scan_k(const float* __restrict__ xc, const float* __restrict__ dl,
                       const float* __restrict__ bc, const float* __restrict__ xz,
                       const float* __restrict__ A_log, const float* __restrict__ Dp,
                       float* __restrict__ y) {
    int tid = threadIdx.x;
    int pair = blockIdx.x * 8 + (tid >> 4);
    int n = tid & 15;
    int b = pair / DI;
    int d = pair - b * DI;
    float a = -__expf(A_log[d * NST + n]);
    float Dv = Dp[d];
    float hs = 0.f;
    size_t base = (size_t)b * LSEQ;
    #pragma unroll 4
    for (int l = 0; l < LSEQ; l++) {
        size_t t = base + l;
        float xv = xc[t * DI + d];
        float de = dl[t * DI + d];
        float Bv = bc[t * 32 + n];
        float Cv = bc[t * 32 + 16 + n];
        hs = __expf(de * a) * hs + de * Bv * xv;
        float yv = hs * Cv;
        yv += __shfl_xor_sync(0xffffffffu, yv, 8);
        yv += __shfl_xor_sync(0xffffffffu, yv, 4);
        yv += __shfl_xor_sync(0xffffffffu, yv, 2);
        yv += __shfl_xor_sync(0xffffffffu, yv, 1);
        if (n == 0) {
            float z = xz[t * (2 * DI) + DI + d];
            y[t * DI + d] = (yv + Dv * xv) * siluf(z);
        }
    }
}

// ---------------- SwiGLU elementwise ----------------
__global__ void swiglu_k(float* __restrict__ g, const float* __restrict__ u, int n) {
    int i = blockIdx.x * blockDim.x + threadIdx.x;
    if (i < n) {
        float gv = g[i];
        g[i] = siluf(gv) * u[i];
    }
}

// ---------------- launch ----------------
extern "C" void kernel_launch(void* const* d_in, const int* in_sizes, int n_in,
                              void* d_out, int out_size) {
    const float* x         = (const float*)d_in[0];
    const float* rms1_w    = (const float*)d_in[1];
    const float* rms2_w    = (const float*)d_in[2];
    const float* in_proj_w = (const float*)d_in[3];
    const float* conv_w    = (const float*)d_in[4];
    const float* conv_b    = (const float*)d_in[5];
    const float* x_proj_w  = (const float*)d_in[6];
    const float* dt_proj_w = (const float*)d_in[7];
    const float* dt_proj_b = (const float*)d_in[8];
    const float* A_log     = (const float*)d_in[9];
    const float* D_param   = (const float*)d_in[10];
    const float* out_proj_w= (const float*)d_in[11];
    const float* ln_gamma  = (const float*)d_in[12];
    const float* ln_beta   = (const float*)d_in[13];
    const float* gate_w    = (const float*)d_in[14];
    const float* up_w      = (const float*)d_in[15];
    const float* down_w    = (const float*)d_in[16];
    float* out = (float*)d_out;

    float *h, *xz, *xc, *de, *bc, *y, *mm, *x1, *ga, *up;
    cudaGetSymbolAddress((void**)&h,  g_h);
    cudaGetSymbolAddress((void**)&xz, g_xz);
    cudaGetSymbolAddress((void**)&xc, g_xconv);
    cudaGetSymbolAddress((void**)&de, g_delta);
    cudaGetSymbolAddress((void**)&bc, g_bc);
    cudaGetSymbolAddress((void**)&y,  g_y);
    cudaGetSymbolAddress((void**)&mm, g_mm);
    cudaGetSymbolAddress((void**)&x1, g_x1);
    cudaGetSymbolAddress((void**)&ga, g_gate);
    cudaGetSymbolAddress((void**)&up, g_up);

    rmsnorm_k<<<TOK, 128>>>(x, rms1_w, h);
    tgemm_k<0><<<dim3(12, 64), 256>>>(h, DM, in_proj_w, 2 * DI, xz, 2 * DI,
                                      TOK, 2 * DI, DM, nullptr, nullptr);
    tconv_k<<<dim3(6, 64), 256>>>(xz, conv_w, conv_b, xc);
    tgemm_k<0><<<dim3(1, 64), 256>>>(xc, DI, x_proj_w, 32, bc, 32,
                                     TOK, 32, DI, nullptr, nullptr);
    tgemm_k<3><<<dim3(6, 64), 256>>>(xc, DI, dt_proj_w, DI, de, DI,
                                     TOK, DI, DI, dt_proj_b, nullptr);
    scan_k<<<(4 * DI) / 8, 128>>>(xc, de, bc, xz, A_log, D_param, y);
    tgemm_k<0><<<dim3(3, 64), 256>>>(y, DI, out_proj_w, DM, mm, DM,
                                     TOK, DM, DI, nullptr, nullptr);
    lnres_k<<<TOK, 128>>>(mm, x, ln_gamma, ln_beta, x1);
    rmsnorm_k<<<TOK, 128>>>(x1, rms2_w, h);
    tgemm_k<0><<<dim3(8, 64), 256>>>(h, DM, gate_w, FFNDIM, ga, FFNDIM,
                                     TOK, FFNDIM, DM, nullptr, nullptr);
    tgemm_k<0><<<dim3(8, 64), 256>>>(h, DM, up_w, FFNDIM, up, FFNDIM,
                                     TOK, FFNDIM, DM, nullptr, nullptr);
    swiglu_k<<<(TOK * FFNDIM + 255) / 256, 256>>>(ga, up, TOK * FFNDIM);
    tgemm_k<4><<<dim3(3, 64), 256>>>(ga, FFNDIM, down_w, DM, out, DM,
                                     TOK, DM, FFNDIM, nullptr, x1);
}

// round 3
// speedup vs baseline: 1.4927x; 1.3149x over previous
#include <cuda_runtime.h>
#include <math.h>
#include <stdint.h>

#define TOK   8192
#define DM    384
#define DI    768
#define NST   16
#define FFNDIM 1024
#define LSEQ  2048

#define PADA 20
#define PADB 136
#define SW_WORDS (128 * PADA + 16 * PADB)   // 4736 words per stage
#define SMEM_BYTES (3 * SW_WORDS * 4)       // 56832

// ---------------- scratch ----------------
__device__ float g_h[TOK * DM];
__device__ float g_xz[TOK * 2 * DI];
__device__ float g_xconv[TOK * DI];      // fp32 for scan
__device__ float g_xct[TOK * DI];        // tf32-rounded for GEMMs
__device__ float g_delta[TOK * DI];
__device__ float g_bc[TOK * 2 * NST];
__device__ float g_y[TOK * DI];
__device__ float g_mm[TOK * DM];
__device__ float g_x1[TOK * DM];
__device__ float g_gate[TOK * FFNDIM];
__device__ float g_up[TOK * FFNDIM];
__device__ float g_wtf[5038080];         // rounded weights, packed

__device__ __forceinline__ float siluf(float x) { return x / (1.f + __expf(-x)); }

__device__ __forceinline__ uint32_t f2tf(float f) {
    uint32_t r;
    asm("cvt.rna.tf32.f32 %0, %1;" : "=r"(r) : "f"(f));
    return r;
}
__device__ __forceinline__ float rndtf(float f) { return __uint_as_float(f2tf(f)); }

__device__ __forceinline__ uint32_t sm_u32(const void* p) {
    return (uint32_t)__cvta_generic_to_shared(p);
}
#define CP16(dst, src, sz) \
    asm volatile("cp.async.cg.shared.global [%0], [%1], 16, %2;" :: "r"(dst), "l"(src), "r"(sz))
#define CPCOMMIT() asm volatile("cp.async.commit_group;")
#define CPWAIT1()  asm volatile("cp.async.wait_group 1;")

#define MMA_TF32(d, a, b)                                                    \
    asm volatile(                                                            \
        "mma.sync.aligned.m16n8k8.row.col.f32.tf32.tf32.f32 "                \
        "{%0,%1,%2,%3},{%4,%5,%6,%7},{%8,%9},{%0,%1,%2,%3};\n"               \
        : "+f"((d)[0]), "+f"((d)[1]), "+f"((d)[2]), "+f"((d)[3])             \
        : "r"((a)[0]), "r"((a)[1]), "r"((a)[2]), "r"((a)[3]),                \
          "r"((b)[0]), "r"((b)[1]))

// ---------------- weight rounding ----------------
__global__ void roundcp_k(const float* __restrict__ s, float* __restrict__ d, int n) {
    for (int i = blockIdx.x * blockDim.x + threadIdx.x; i < n; i += gridDim.x * blockDim.x)
        d[i] = rndtf(s[i]);
}

// ---------------- RMSNorm (tf32-rounded output) ----------------
__global__ void rmsnorm_k(const float* __restrict__ x, const float* __restrict__ w,
                          float* __restrict__ o) {
    int t = blockIdx.x, tid = threadIdx.x;
    const float* xr = x + (size_t)t * DM;
    float v0 = xr[tid], v1 = xr[tid + 128], v2 = xr[tid + 256];
    float ss = v0 * v0 + v1 * v1 + v2 * v2;
    #pragma unroll
    for (int s = 16; s > 0; s >>= 1) ss += __shfl_xor_sync(0xffffffffu, ss, s);
    __shared__ float sm[4];
    if ((tid & 31) == 0) sm[tid >> 5] = ss;
    __syncthreads();
    float tot = sm[0] + sm[1] + sm[2] + sm[3];
    float sc = rsqrtf(tot / (float)DM + 1e-6f);
    float* orow = o + (size_t)t * DM;
    orow[tid]       = rndtf(v0 * sc * w[tid]);
    orow[tid + 128] = rndtf(v1 * sc * w[tid + 128]);
    orow[tid + 256] = rndtf(v2 * sc * w[tid + 256]);
}

// ------------- LayerNorm + residual -------------
__global__ void lnres_k(const float* __restrict__ mm, const float* __restrict__ res,
                        const float* __restrict__ gamma, const float* __restrict__ beta,
                        float* __restrict__ o) {
    int t = blockIdx.x, tid = threadIdx.x;
    const float* r_ = mm + (size_t)t * DM;
    float v0 = r_[tid], v1 = r_[tid + 128], v2 = r_[tid + 256];
    float s = v0 + v1 + v2;
    float ss = v0 * v0 + v1 * v1 + v2 * v2;
    #pragma unroll
    for (int k = 16; k > 0; k >>= 1) {
        s  += __shfl_xor_sync(0xffffffffu, s, k);
        ss += __shfl_xor_sync(0xffffffffu, ss, k);
    }
    __shared__ float sm1[4], sm2[4];
    if ((tid & 31) == 0) { sm1[tid >> 5] = s; sm2[tid >> 5] = ss; }
    __syncthreads();
    s  = sm1[0] + sm1[1] + sm1[2] + sm1[3];
    ss = sm2[0] + sm2[1] + sm2[2] + sm2[3];
    float mu  = s / (float)DM;
    float var = ss / (float)DM - mu * mu;
    float rs  = rsqrtf(var + 1e-5f);
    const float* rr = res + (size_t)t * DM;
    float* orow = o + (size_t)t * DM;
    orow[tid]       = rr[tid]       + (v0 - mu) * rs * gamma[tid]       + beta[tid];
    orow[tid + 128] = rr[tid + 128] + (v1 - mu) * rs * gamma[tid + 128] + beta[tid + 128];
    orow[tid + 256] = rr[tid + 256] + (v2 - mu) * rs * gamma[tid + 256] + beta[tid + 256];
}

// --------- shared compute body for one 16-wide k-slab pair (BK=16) ---------
__device__ __forceinline__ void mma_tile(const uint32_t* As, const uint32_t* Bs,
                                         int wm, int wn, int lr, int lc,
                                         float acc[4][4][4]) {
    #pragma unroll
    for (int ks = 0; ks < 2; ks++) {
        uint32_t af[4][4], bf[4][2];
        #pragma unroll
        for (int mt = 0; mt < 4; mt++) {
            int R = wm * 64 + mt * 16;
            af[mt][0] = As[(R + lr) * PADA + ks * 8 + lc];
            af[mt][1] = As[(R + lr + 8) * PADA + ks * 8 + lc];
            af[mt][2] = As[(R + lr) * PADA + ks * 8 + 4 + lc];
            af[mt][3] = As[(R + lr + 8) * PADA + ks * 8 + 4 + lc];
        }
        #pragma unroll
        for (int nt = 0; nt < 4; nt++) {
            int CB = wn * 32 + nt * 8;
            bf[nt][0] = Bs[(ks * 8 + lc) * PADB + CB + lr];
            bf[nt][1] = Bs[(ks * 8 + 4 + lc) * PADB + CB + lr];
        }
        #pragma unroll
        for (int mt = 0; mt < 4; mt++)
            #pragma unroll
            for (int nt = 0; nt < 4; nt++) MMA_TF32(acc[mt][nt], af[mt], bf[nt]);
    }
}

// ---------------- pipelined TF32 GEMM ----------------
// EPI: 0 = plain, 3 = +bias softplus, 4 = +res.  RND: round output to tf32.
template <int EPI, int RND>
__global__ void __launch_bounds__(256, 2) tgemm_k(
    const float* __restrict__ A, int lda,
    const float* __restrict__ B, int ldb,
    float* __restrict__ C, int ldc,
    int M, int N, int K,
    const float* __restrict__ bias,
    const float* __restrict__ res) {
    extern __shared__ uint32_t sh[];
    int tid = threadIdx.x, lane = tid & 31, wid = tid >> 5;
    int wm = wid >> 2, wn = wid & 3;
    int m0 = blockIdx.y * 128, n0 = blockIdx.x * 128;
    float acc[4][4][4] = {};
    int ar = tid >> 1, ak = (tid & 1) * 8;
    int bk = tid >> 5, bn = (tid & 31) * 4;
    int lr = lane >> 2, lc = lane & 3;

    const float* abase = A + (size_t)(m0 + ar) * lda + ak;
    int ccol = n0 + bn;
    uint32_t bsz = (ccol < N) ? 16u : 0u;
    int bcol = bsz ? ccol : 0;

    auto load_tile = [&](int st, int k0) {
        uint32_t* As = sh + st * SW_WORDS;
        uint32_t* Bs = As + 128 * PADA;
        const float* ap = abase + k0;
        CP16(sm_u32(&As[ar * PADA + ak]), ap, 16u);
        CP16(sm_u32(&As[ar * PADA + ak + 4]), ap + 4, 16u);
        CP16(sm_u32(&Bs[bk * PADB + bn]), B + (size_t)(k0 + bk) * ldb + bcol, bsz);
        CP16(sm_u32(&Bs[(bk + 8) * PADB + bn]), B + (size_t)(k0 + bk + 8) * ldb + bcol, bsz);
    };

    int KT = K / 16;
    load_tile(0, 0); CPCOMMIT();
    load_tile(1, 16); CPCOMMIT();
    for (int it = 0; it < KT; it++) {
        CPWAIT1();
        __syncthreads();
        int pre = it + 2;
        if (pre < KT) load_tile(pre % 3, pre * 16);
        CPCOMMIT();
        const uint32_t* As = sh + (it % 3) * SW_WORDS;
        mma_tile(As, As + 128 * PADA, wm, wn, lr, lc, acc);
    }

    int c2 = lc * 2;
    #pragma unroll
    for (int mt = 0; mt < 4; mt++) {
        int row0 = m0 + wm * 64 + mt * 16 + lr;
        #pragma unroll
        for (int nt = 0; nt < 4; nt++) {
            int col = n0 + wn * 32 + nt * 8 + c2;
            if (col < N) {
                #pragma unroll
                for (int h = 0; h < 2; h++) {
                    int row = row0 + h * 8;
                    float e0 = acc[mt][nt][h * 2 + 0];
                    float e1 = acc[mt][nt][h * 2 + 1];
                    if (EPI == 3) {
                        e0 += bias[col];     e1 += bias[col + 1];
                        e0 = (e0 > 20.f) ? e0 : log1pf(__expf(e0));
                        e1 = (e1 > 20.f) ? e1 : log1pf(__expf(e1));
                    }
                    if (EPI == 4) {
                        e0 += res[(size_t)row * ldc + col];
                        e1 += res[(size_t)row * ldc + col + 1];
                    }
                    if (RND) { e0 = rndtf(e0); e1 = rndtf(e1); }
                    *(float2*)(C + (size_t)row * ldc + col) = make_float2(e0, e1);
                }
            }
        }
    }
}

// -------- conv1d (k=4, SAME (1,2)) as pipelined implicit-im2col TF32 GEMM ------
__global__ void __launch_bounds__(256, 2) tconv_k(
    const float* __restrict__ xz, const float* __restrict__ W,
    const float* __restrict__ bias, float* __restrict__ outf,
    float* __restrict__ outt) {
    extern __shared__ uint32_t sh[];
    int tid = threadIdx.x, lane = tid & 31, wid = tid >> 5;
    int wm = wid >> 2, wn = wid & 3;
    int m0 = blockIdx.y * 128, n0 = blockIdx.x * 128;
    float acc[4][4][4] = {};
    int ar = tid >> 1, ak = (tid & 1) * 8;
    int bk = tid >> 5, bn = (tid & 31) * 4;
    int lr = lane >> 2, lc = lane & 3;

    int tok = m0 + ar;
    int l = tok & (LSEQ - 1);
    int tb = tok - l;

    auto load_tile = [&](int st, int kk) {
        int w = kk / 48;
        int k0 = (kk - w * 48) * 16;
        uint32_t* As = sh + st * SW_WORDS;
        uint32_t* Bs = As + 128 * PADA;
        int ls = l + w - 1;
        uint32_t asz = ((unsigned)ls < LSEQ) ? 16u : 0u;
        int lss = asz ? ls : 0;
        const float* ap = xz + (size_t)(tb + lss) * (2 * DI) + k0 + ak;
        CP16(sm_u32(&As[ar * PADA + ak]), ap, asz);
        CP16(sm_u32(&As[ar * PADA + ak + 4]), ap + 4, asz);
        const float* bp = W + (size_t)(w * DI + k0 + bk) * DI + n0 + bn;
        CP16(sm_u32(&Bs[bk * PADB + bn]), bp, 16u);
        CP16(sm_u32(&Bs[(bk + 8) * PADB + bn]), bp + 8 * DI, 16u);
    };

    const int KT = 192;
    load_tile(0, 0); CPCOMMIT();
    load_tile(1, 1); CPCOMMIT();
    for (int it = 0; it < KT; it++) {
        CPWAIT1();
        __syncthreads();
        int pre = it + 2;
        if (pre < KT) load_tile(pre % 3, pre);
        CPCOMMIT();
        const uint32_t* As = sh + (it % 3) * SW_WORDS;
        mma_tile(As, As + 128 * PADA, wm, wn, lr, lc, acc);
    }

    int c2 = lc * 2;
    #pragma unroll
    for (int mt = 0; mt < 4; mt++) {
        int row0 = m0 + wm * 64 + mt * 16 + lr;
        #pragma unroll
        for (int nt = 0; nt < 4; nt++) {
            int col = n0 + wn * 32 + nt * 8 + c2;
            #pragma unroll
            for (int h = 0; h < 2; h++) {
                int row = row0 + h * 8;
                float e0 = siluf(acc[mt][nt][h * 2 + 0] + bias[col]);
                float e1 = siluf(acc[mt][nt][h * 2 + 1] + bias[col + 1]);
                *(float2*)(outf + (size_t)row * DI + col) = make_float2(e0, e1);
                *(float2*)(outt + (size_t)row * DI + col) =
                    make_float2(rndtf(e0), rndtf(e1));
            }
        }
    }
}

// ---------------- selective scan ----------------
__global__ void scan_k(const float* __restrict__ xc, const float* __restrict__ dl,
                       const float* __restrict__ bc, const float* __restrict__ xz,
                       const float* __restrict__ A_log, const float* __restrict__ Dp,
                       float* __restrict__ y) {
    int tid = threadIdx.x;
    int pair = blockIdx.x * 8 + (tid >> 4);
    int n = tid & 15;
    int b = pair / DI;
    int d = pair - b * DI;
    float a = -__expf(A_log[d * NST + n]);
    float Dv = Dp[d];
    float hs = 0.f;
    size_t base = (size_t)b * LSEQ;
    #pragma unroll 4
    for (int l = 0; l < LSEQ; l++) {
        size_t t = base + l;
        float xv = xc[t * DI + d];
        float de = dl[t * DI + d];
        float Bv = bc[t * 32 + n];
        float Cv = bc[t * 32 + 16 + n];
        hs = __expf(de * a) * hs + de * Bv * xv;
        float yv = hs * Cv;
        yv += __shfl_xor_sync(0xffffffffu, yv, 8);
        yv += __shfl_xor_sync(0xffffffffu, yv, 4);
        yv += __shfl_xor_sync(0xffffffffu, yv, 2);
        yv += __shfl_xor_sync(0xffffffffu, yv, 1);
        if (n == 0) {
            float z = xz[t * (2 * DI) + DI + d];
            y[t * DI + d] = rndtf((yv + Dv * xv) * siluf(z));
        }
    }
}

// ---------------- SwiGLU elementwise ----------------
__global__ void swiglu_k(float* __restrict__ g, const float* __restrict__ u, int n) {
    int i = blockIdx.x * blockDim.x + threadIdx.x;
    if (i < n) {
        float gv = g[i];
        g[i] = rndtf(siluf(gv) * u[i]);
    }
}

// ---------------- launch ----------------
extern "C" void kernel_launch(void* const* d_in, const int* in_sizes, int n_in,
                              void* d_out, int out_size) {
    const float* x         = (const float*)d_in[0];
    const float* rms1_w    = (const float*)d_in[1];
    const float* rms2_w    = (const float*)d_in[2];
    const float* in_proj_w = (const float*)d_in[3];
    const float* conv_w    = (const float*)d_in[4];
    const float* conv_b    = (const float*)d_in[5];
    const float* x_proj_w  = (const float*)d_in[6];
    const float* dt_proj_w = (const float*)d_in[7];
    const float* dt_proj_b = (const float*)d_in[8];
    const float* A_log     = (const float*)d_in[9];
    const float* D_param   = (const float*)d_in[10];
    const float* out_proj_w= (const float*)d_in[11];
    const float* ln_gamma  = (const float*)d_in[12];
    const float* ln_beta   = (const float*)d_in[13];
    const float* gate_w    = (const float*)d_in[14];
    const float* up_w      = (const float*)d_in[15];
    const float* down_w    = (const float*)d_in[16];
    float* out = (float*)d_out;

    float *h, *xz, *xc, *xct, *de, *bc, *y, *mm, *x1, *ga, *up, *wtf;
    cudaGetSymbolAddress((void**)&h,   g_h);
    cudaGetSymbolAddress((void**)&xz,  g_xz);
    cudaGetSymbolAddress((void**)&xc,  g_xconv);
    cudaGetSymbolAddress((void**)&xct, g_xct);
    cudaGetSymbolAddress((void**)&de,  g_delta);
    cudaGetSymbolAddress((void**)&bc,  g_bc);
    cudaGetSymbolAddress((void**)&y,   g_y);
    cudaGetSymbolAddress((void**)&mm,  g_mm);
    cudaGetSymbolAddress((void**)&x1,  g_x1);
    cudaGetSymbolAddress((void**)&ga,  g_gate);
    cudaGetSymbolAddress((void**)&up,  g_up);
    cudaGetSymbolAddress((void**)&wtf, g_wtf);

    cudaFuncSetAttribute(tgemm_k<0,1>, cudaFuncAttributeMaxDynamicSharedMemorySize, SMEM_BYTES);
    cudaFuncSetAttribute(tgemm_k<0,0>, cudaFuncAttributeMaxDynamicSharedMemorySize, SMEM_BYTES);
    cudaFuncSetAttribute(tgemm_k<3,0>, cudaFuncAttributeMaxDynamicSharedMemorySize, SMEM_BYTES);
    cudaFuncSetAttribute(tgemm_k<4,0>, cudaFuncAttributeMaxDynamicSharedMemorySize, SMEM_BYTES);
    cudaFuncSetAttribute(tconv_k,      cudaFuncAttributeMaxDynamicSharedMemorySize, SMEM_BYTES);

    // weight offsets in g_wtf
    float* w_inp  = wtf;
    float* w_conv = w_inp  + 589824;
    float* w_xp   = w_conv + 2359296;
    float* w_dt   = w_xp   + 24576;
    float* w_out  = w_dt   + 589824;
    float* w_gate = w_out  + 294912;
    float* w_up   = w_gate + 393216;
    float* w_down = w_up   + 393216;

    roundcp_k<<<256, 256>>>(in_proj_w,  w_inp,  589824);
    roundcp_k<<<256, 256>>>(conv_w,     w_conv, 2359296);
    roundcp_k<<<64,  256>>>(x_proj_w,   w_xp,   24576);
    roundcp_k<<<256, 256>>>(dt_proj_w,  w_dt,   589824);
    roundcp_k<<<256, 256>>>(out_proj_w, w_out,  294912);
    roundcp_k<<<256, 256>>>(gate_w,     w_gate, 393216);
    roundcp_k<<<256, 256>>>(up_w,       w_up,   393216);
    roundcp_k<<<256, 256>>>(down_w,     w_down, 393216);

    rmsnorm_k<<<TOK, 128>>>(x, rms1_w, h);
    tgemm_k<0,1><<<dim3(12, 64), 256, SMEM_BYTES>>>(h, DM, w_inp, 2 * DI, xz, 2 * DI,
                                                    TOK, 2 * DI, DM, nullptr, nullptr);
    tconv_k<<<dim3(6, 64), 256, SMEM_BYTES>>>(xz, w_conv, conv_b, xc, xct);
    tgemm_k<0,0><<<dim3(1, 64), 256, SMEM_BYTES>>>(xct, DI, w_xp, 32, bc, 32,
                                                   TOK, 32, DI, nullptr, nullptr);
    tgemm_k<3,0><<<dim3(6, 64), 256, SMEM_BYTES>>>(xct, DI, w_dt, DI, de, DI,
                                                   TOK, DI, DI, dt_proj_b, nullptr);
    scan_k<<<(4 * DI) / 8, 128>>>(xc, de, bc, xz, A_log, D_param, y);
    tgemm_k<0,0><<<dim3(3, 64), 256, SMEM_BYTES>>>(y, DI, w_out, DM, mm, DM,
                                                   TOK, DM, DI, nullptr, nullptr);
    lnres_k<<<TOK, 128>>>(mm, x, ln_gamma, ln_beta, x1);
    rmsnorm_k<<<TOK, 128>>>(x1, rms2_w, h);
    tgemm_k<0,0><<<dim3(8, 64), 256, SMEM_BYTES>>>(h, DM, w_gate, FFNDIM, ga, FFNDIM,
                                                   TOK, FFNDIM, DM, nullptr, nullptr);
    tgemm_k<0,0><<<dim3(8, 64), 256, SMEM_BYTES>>>(h, DM, w_up, FFNDIM, up, FFNDIM,
                                                   TOK, FFNDIM, DM, nullptr, nullptr);
    swiglu_k<<<(TOK * FFNDIM + 255) / 256, 256>>>(ga, up, TOK * FFNDIM);
    tgemm_k<4,0><<<dim3(3, 64), 256, SMEM_BYTES>>>(ga, FFNDIM, w_down, DM, out, DM,
                                                   TOK, DM, FFNDIM, nullptr, x1);
}

// round 4
// speedup vs baseline: 1.5250x; 1.0216x over previous
#include <cuda_runtime.h>
#include <math.h>
#include <stdint.h>

#define TOK   8192
#define DM    384
#define DI    768
#define NST   16
#define FFNDIM 1024
#define LSEQ  2048

#define PADA 20
#define PADB 136
#define SW_WORDS (128 * PADA + 16 * PADB)   // 4736 words per stage
#define SMEM_BYTES (3 * SW_WORDS * 4)       // 56832

// ---------------- scratch ----------------
__device__ float g_h[TOK * DM];
__device__ float g_xz[TOK * 2 * DI];
__device__ float g_xconv[TOK * DI];      // fp32 for scan
__device__ float g_xct[TOK * DI];        // tf32-rounded for GEMMs
__device__ float g_delta[TOK * DI];
__device__ float g_bc[TOK * 2 * NST];
__device__ float g_y[TOK * DI];
__device__ float g_mm[TOK * DM];
__device__ float g_x1[TOK * DM];
__device__ float g_gate[TOK * FFNDIM];
__device__ float g_up[TOK * FFNDIM];
__device__ float g_wtf[5038080];         // rounded weights, packed

__device__ __forceinline__ float siluf(float x) { return x / (1.f + __expf(-x)); }

__device__ __forceinline__ uint32_t f2tf(float f) {
    uint32_t r;
    asm("cvt.rna.tf32.f32 %0, %1;" : "=r"(r) : "f"(f));
    return r;
}
__device__ __forceinline__ float rndtf(float f) { return __uint_as_float(f2tf(f)); }

__device__ __forceinline__ uint32_t sm_u32(const void* p) {
    return (uint32_t)__cvta_generic_to_shared(p);
}
#define CP16(dst, src, sz) \
    asm volatile("cp.async.cg.shared.global [%0], [%1], 16, %2;" :: "r"(dst), "l"(src), "r"(sz))
#define CPCOMMIT() asm volatile("cp.async.commit_group;")
#define CPWAIT1()  asm volatile("cp.async.wait_group 1;")

#define MMA_TF32(d, a, b)                                                    \
    asm volatile(                                                            \
        "mma.sync.aligned.m16n8k8.row.col.f32.tf32.tf32.f32 "                \
        "{%0,%1,%2,%3},{%4,%5,%6,%7},{%8,%9},{%0,%1,%2,%3};\n"               \
        : "+f"((d)[0]), "+f"((d)[1]), "+f"((d)[2]), "+f"((d)[3])             \
        : "r"((a)[0]), "r"((a)[1]), "r"((a)[2]), "r"((a)[3]),                \
          "r"((b)[0]), "r"((b)[1]))

// ---------------- weight rounding ----------------
__global__ void roundcp_k(const float* __restrict__ s, float* __restrict__ d, int n) {
    for (int i = blockIdx.x * blockDim.x + threadIdx.x; i < n; i += gridDim.x * blockDim.x)
        d[i] = rndtf(s[i]);
}

// ---------------- RMSNorm (tf32-rounded output) ----------------
__global__ void rmsnorm_k(const float* __restrict__ x, const float* __restrict__ w,
                          float* __restrict__ o) {
    int t = blockIdx.x, tid = threadIdx.x;
    const float* xr = x + (size_t)t * DM;
    float v0 = xr[tid], v1 = xr[tid + 128], v2 = xr[tid + 256];
    float ss = v0 * v0 + v1 * v1 + v2 * v2;
    #pragma unroll
    for (int s = 16; s > 0; s >>= 1) ss += __shfl_xor_sync(0xffffffffu, ss, s);
    __shared__ float sm[4];
    if ((tid & 31) == 0) sm[tid >> 5] = ss;
    __syncthreads();
    float tot = sm[0] + sm[1] + sm[2] + sm[3];
    float sc = rsqrtf(tot / (float)DM + 1e-6f);
    float* orow = o + (size_t)t * DM;
    orow[tid]       = rndtf(v0 * sc * w[tid]);
    orow[tid + 128] = rndtf(v1 * sc * w[tid + 128]);
    orow[tid + 256] = rndtf(v2 * sc * w[tid + 256]);
}

// ------------- LayerNorm + residual -------------
__global__ void lnres_k(const float* __restrict__ mm, const float* __restrict__ res,
                        const float* __restrict__ gamma, const float* __restrict__ beta,
                        float* __restrict__ o) {
    int t = blockIdx.x, tid = threadIdx.x;
    const float* r_ = mm + (size_t)t * DM;
    float v0 = r_[tid], v1 = r_[tid + 128], v2 = r_[tid + 256];
    float s = v0 + v1 + v2;
    float ss = v0 * v0 + v1 * v1 + v2 * v2;
    #pragma unroll
    for (int k = 16; k > 0; k >>= 1) {
        s  += __shfl_xor_sync(0xffffffffu, s, k);
        ss += __shfl_xor_sync(0xffffffffu, ss, k);
    }
    __shared__ float sm1[4], sm2[4];
    if ((tid & 31) == 0) { sm1[tid >> 5] = s; sm2[tid >> 5] = ss; }
    __syncthreads();
    s  = sm1[0] + sm1[1] + sm1[2] + sm1[3];
    ss = sm2[0] + sm2[1] + sm2[2] + sm2[3];
    float mu  = s / (float)DM;
    float var = ss / (float)DM - mu * mu;
    float rs  = rsqrtf(var + 1e-5f);
    const float* rr = res + (size_t)t * DM;
    float* orow = o + (size_t)t * DM;
    orow[tid]       = rr[tid]       + (v0 - mu) * rs * gamma[tid]       + beta[tid];
    orow[tid + 128] = rr[tid + 128] + (v1 - mu) * rs * gamma[tid + 128] + beta[tid + 128];
    orow[tid + 256] = rr[tid + 256] + (v2 - mu) * rs * gamma[tid + 256] + beta[tid + 256];
}

// --------- shared compute body for one 16-wide k-slab pair (BK=16) ---------
__device__ __forceinline__ void mma_tile(const uint32_t* As, const uint32_t* Bs,
                                         int wm, int wn, int lr, int lc,
                                         float acc[4][4][4]) {
    #pragma unroll
    for (int ks = 0; ks < 2; ks++) {
        uint32_t af[4][4], bf[4][2];
        #pragma unroll
        for (int mt = 0; mt < 4; mt++) {
            int R = wm * 64 + mt * 16;
            af[mt][0] = As[(R + lr) * PADA + ks * 8 + lc];
            af[mt][1] = As[(R + lr + 8) * PADA + ks * 8 + lc];
            af[mt][2] = As[(R + lr) * PADA + ks * 8 + 4 + lc];
            af[mt][3] = As[(R + lr + 8) * PADA + ks * 8 + 4 + lc];
        }
        #pragma unroll
        for (int nt = 0; nt < 4; nt++) {
            int CB = wn * 32 + nt * 8;
            bf[nt][0] = Bs[(ks * 8 + lc) * PADB + CB + lr];
            bf[nt][1] = Bs[(ks * 8 + 4 + lc) * PADB + CB + lr];
        }
        #pragma unroll
        for (int mt = 0; mt < 4; mt++)
            #pragma unroll
            for (int nt = 0; nt < 4; nt++) MMA_TF32(acc[mt][nt], af[mt], bf[nt]);
    }
}

// ---------------- pipelined TF32 GEMM ----------------
// EPI: 0 = plain, 3 = +bias softplus, 4 = +res.  RND: round output to tf32.
template <int EPI, int RND>
__global__ void __launch_bounds__(256, 2) tgemm_k(
    const float* __restrict__ A, int lda,
    const float* __restrict__ B, int ldb,
    float* __restrict__ C, int ldc,
    int M, int N, int K,
    const float* __restrict__ bias,
    const float* __restrict__ res) {
    extern __shared__ uint32_t sh[];
    int tid = threadIdx.x, lane = tid & 31, wid = tid >> 5;
    int wm = wid >> 2, wn = wid & 3;
    int m0 = blockIdx.y * 128, n0 = blockIdx.x * 128;
    float acc[4][4][4] = {};
    int ar = tid >> 1, ak = (tid & 1) * 8;
    int bk = tid >> 5, bn = (tid & 31) * 4;
    int lr = lane >> 2, lc = lane & 3;

    const float* abase = A + (size_t)(m0 + ar) * lda + ak;
    int ccol = n0 + bn;
    uint32_t bsz = (ccol < N) ? 16u : 0u;
    int bcol = bsz ? ccol : 0;

    auto load_tile = [&](int st, int k0) {
        uint32_t* As = sh + st * SW_WORDS;
        uint32_t* Bs = As + 128 * PADA;
        const float* ap = abase + k0;
        CP16(sm_u32(&As[ar * PADA + ak]), ap, 16u);
        CP16(sm_u32(&As[ar * PADA + ak + 4]), ap + 4, 16u);
        CP16(sm_u32(&Bs[bk * PADB + bn]), B + (size_t)(k0 + bk) * ldb + bcol, bsz);
        CP16(sm_u32(&Bs[(bk + 8) * PADB + bn]), B + (size_t)(k0 + bk + 8) * ldb + bcol, bsz);
    };

    int KT = K / 16;
    load_tile(0, 0); CPCOMMIT();
    load_tile(1, 16); CPCOMMIT();
    for (int it = 0; it < KT; it++) {
        CPWAIT1();
        __syncthreads();
        int pre = it + 2;
        if (pre < KT) load_tile(pre % 3, pre * 16);
        CPCOMMIT();
        const uint32_t* As = sh + (it % 3) * SW_WORDS;
        mma_tile(As, As + 128 * PADA, wm, wn, lr, lc, acc);
    }

    int c2 = lc * 2;
    #pragma unroll
    for (int mt = 0; mt < 4; mt++) {
        int row0 = m0 + wm * 64 + mt * 16 + lr;
        #pragma unroll
        for (int nt = 0; nt < 4; nt++) {
            int col = n0 + wn * 32 + nt * 8 + c2;
            if (col < N) {
                #pragma unroll
                for (int h = 0; h < 2; h++) {
                    int row = row0 + h * 8;
                    float e0 = acc[mt][nt][h * 2 + 0];
                    float e1 = acc[mt][nt][h * 2 + 1];
                    if (EPI == 3) {
                        e0 += bias[col];     e1 += bias[col + 1];
                        e0 = (e0 > 20.f) ? e0 : log1pf(__expf(e0));
                        e1 = (e1 > 20.f) ? e1 : log1pf(__expf(e1));
                    }
                    if (EPI == 4) {
                        e0 += res[(size_t)row * ldc + col];
                        e1 += res[(size_t)row * ldc + col + 1];
                    }
                    if (RND) { e0 = rndtf(e0); e1 = rndtf(e1); }
                    *(float2*)(C + (size_t)row * ldc + col) = make_float2(e0, e1);
                }
            }
        }
    }
}

// -------- conv1d (k=4, SAME (1,2)) as pipelined implicit-im2col TF32 GEMM ------
__global__ void __launch_bounds__(256, 2) tconv_k(
    const float* __restrict__ xz, const float* __restrict__ W,
    const float* __restrict__ bias, float* __restrict__ outf,
    float* __restrict__ outt) {
    extern __shared__ uint32_t sh[];
    int tid = threadIdx.x, lane = tid & 31, wid = tid >> 5;
    int wm = wid >> 2, wn = wid & 3;
    int m0 = blockIdx.y * 128, n0 = blockIdx.x * 128;
    float acc[4][4][4] = {};
    int ar = tid >> 1, ak = (tid & 1) * 8;
    int bk = tid >> 5, bn = (tid & 31) * 4;
    int lr = lane >> 2, lc = lane & 3;

    int tok = m0 + ar;
    int l = tok & (LSEQ - 1);
    int tb = tok - l;

    auto load_tile = [&](int st, int kk) {
        int w = kk / 48;
        int k0 = (kk - w * 48) * 16;
        uint32_t* As = sh + st * SW_WORDS;
        uint32_t* Bs = As + 128 * PADA;
        int ls = l + w - 1;
        uint32_t asz = ((unsigned)ls < LSEQ) ? 16u : 0u;
        int lss = asz ? ls : 0;
        const float* ap = xz + (size_t)(tb + lss) * (2 * DI) + k0 + ak;
        CP16(sm_u32(&As[ar * PADA + ak]), ap, asz);
        CP16(sm_u32(&As[ar * PADA + ak + 4]), ap + 4, asz);
        const float* bp = W + (size_t)(w * DI + k0 + bk) * DI + n0 + bn;
        CP16(sm_u32(&Bs[bk * PADB + bn]), bp, 16u);
        CP16(sm_u32(&Bs[(bk + 8) * PADB + bn]), bp + 8 * DI, 16u);
    };

    const int KT = 192;
    load_tile(0, 0); CPCOMMIT();
    load_tile(1, 1); CPCOMMIT();
    for (int it = 0; it < KT; it++) {
        CPWAIT1();
        __syncthreads();
        int pre = it + 2;
        if (pre < KT) load_tile(pre % 3, pre);
        CPCOMMIT();
        const uint32_t* As = sh + (it % 3) * SW_WORDS;
        mma_tile(As, As + 128 * PADA, wm, wn, lr, lc, acc);
    }

    int c2 = lc * 2;
    #pragma unroll
    for (int mt = 0; mt < 4; mt++) {
        int row0 = m0 + wm * 64 + mt * 16 + lr;
        #pragma unroll
        for (int nt = 0; nt < 4; nt++) {
            int col = n0 + wn * 32 + nt * 8 + c2;
            #pragma unroll
            for (int h = 0; h < 2; h++) {
                int row = row0 + h * 8;
                float e0 = siluf(acc[mt][nt][h * 2 + 0] + bias[col]);
                float e1 = siluf(acc[mt][nt][h * 2 + 1] + bias[col + 1]);
                *(float2*)(outf + (size_t)row * DI + col) = make_float2(e0, e1);
                *(float2*)(outt + (size_t)row * DI + col) =
                    make_float2(rndtf(e0), rndtf(e1));
            }
        }
    }
}

// ---------------- selective scan ----------------
__global__ void scan_k(const float* __restrict__ xc, const float* __restrict__ dl,
                       const float* __restrict__ bc, const float* __restrict__ xz,
                       const float* __restrict__ A_log, const float* __restrict__ Dp,
                       float* __restrict__ y) {
    int tid = threadIdx.x;
    int pair = blockIdx.x * 8 + (tid >> 4);
    int n = tid & 15;
    int b = pair / DI;
    int d = pair - b * DI;
    float a = -__expf(A_log[d * NST + n]);
    float Dv = Dp[d];
    float hs = 0.f;
    size_t base = (size_t)b * LSEQ;
    #pragma unroll 4
    for (int l = 0; l < LSEQ; l++) {
        size_t t = base + l;
        float xv = xc[t * DI + d];
        float de = dl[t * DI + d];
        float Bv = bc[t * 32 + n];
        float Cv = bc[t * 32 + 16 + n];
        hs = __expf(de * a) * hs + de * Bv * xv;
        float yv = hs * Cv;
        yv += __shfl_xor_sync(0xffffffffu, yv, 8);
        yv += __shfl_xor_sync(0xffffffffu, yv, 4);
        yv += __shfl_xor_sync(0xffffffffu, yv, 2);
        yv += __shfl_xor_sync(0xffffffffu, yv, 1);
        if (n == 0) {
            float z = xz[t * (2 * DI) + DI + d];
            y[t * DI + d] = rndtf((yv + Dv * xv) * siluf(z));
        }
    }
}

// ---------------- SwiGLU elementwise ----------------
__global__ void swiglu_k(float* __restrict__ g, const float* __restrict__ u, int n) {
    int i = blockIdx.x * blockDim.x + threadIdx.x;
    if (i < n) {
        float gv = g[i];
        g[i] = rndtf(siluf(gv) * u[i]);
    }
}

// ---------------- launch ----------------
extern "C" void kernel_launch(void* const* d_in, const int* in_sizes, int n_in,
                              void* d_out, int out_size) {
    const float* x         = (const float*)d_in[0];
    const float* rms1_w    = (const float*)d_in[1];
    const float* rms2_w    = (const float*)d_in[2];
    const float* in_proj_w = (const float*)d_in[3];
    const float* conv_w    = (const float*)d_in[4];
    const float* conv_b    = (const float*)d_in[5];
    const float* x_proj_w  = (const float*)d_in[6];
    const float* dt_proj_w = (const float*)d_in[7];
    const float* dt_proj_b = (const float*)d_in[8];
    const float* A_log     = (const float*)d_in[9];
    const float* D_param   = (const float*)d_in[10];
    const float* out_proj_w= (const float*)d_in[11];
    const float* ln_gamma  = (const float*)d_in[12];
    const float* ln_beta   = (const float*)d_in[13];
    const float* gate_w    = (const float*)d_in[14];
    const float* up_w      = (const float*)d_in[15];
    const float* down_w    = (const float*)d_in[16];
    float* out = (float*)d_out;

    float *h, *xz, *xc, *xct, *de, *bc, *y, *mm, *x1, *ga, *up, *wtf;
    cudaGetSymbolAddress((void**)&h,   g_h);
    cudaGetSymbolAddress((void**)&xz,  g_xz);
    cudaGetSymbolAddress((void**)&xc,  g_xconv);
    cudaGetSymbolAddress((void**)&xct, g_xct);
    cudaGetSymbolAddress((void**)&de,  g_delta);
    cudaGetSymbolAddress((void**)&bc,  g_bc);
    cudaGetSymbolAddress((void**)&y,   g_y);
    cudaGetSymbolAddress((void**)&mm,  g_mm);
    cudaGetSymbolAddress((void**)&x1,  g_x1);
    cudaGetSymbolAddress((void**)&ga,  g_gate);
    cudaGetSymbolAddress((void**)&up,  g_up);
    cudaGetSymbolAddress((void**)&wtf, g_wtf);

    cudaFuncSetAttribute(tgemm_k<0,1>, cudaFuncAttributeMaxDynamicSharedMemorySize, SMEM_BYTES);
    cudaFuncSetAttribute(tgemm_k<0,0>, cudaFuncAttributeMaxDynamicSharedMemorySize, SMEM_BYTES);
    cudaFuncSetAttribute(tgemm_k<3,0>, cudaFuncAttributeMaxDynamicSharedMemorySize, SMEM_BYTES);
    cudaFuncSetAttribute(tgemm_k<4,0>, cudaFuncAttributeMaxDynamicSharedMemorySize, SMEM_BYTES);
    cudaFuncSetAttribute(tconv_k,      cudaFuncAttributeMaxDynamicSharedMemorySize, SMEM_BYTES);

    // weight offsets in g_wtf
    float* w_inp  = wtf;
    float* w_conv = w_inp  + 589824;
    float* w_xp   = w_conv + 2359296;
    float* w_dt   = w_xp   + 24576;
    float* w_out  = w_dt   + 589824;
    float* w_gate = w_out  + 294912;
    float* w_up   = w_gate + 393216;
    float* w_down = w_up   + 393216;

    roundcp_k<<<256, 256>>>(in_proj_w,  w_inp,  589824);
    roundcp_k<<<256, 256>>>(conv_w,     w_conv, 2359296);
    roundcp_k<<<64,  256>>>(x_proj_w,   w_xp,   24576);
    roundcp_k<<<256, 256>>>(dt_proj_w,  w_dt,   589824);
    roundcp_k<<<256, 256>>>(out_proj_w, w_out,  294912);
    roundcp_k<<<256, 256>>>(gate_w,     w_gate, 393216);
    roundcp_k<<<256, 256>>>(up_w,       w_up,   393216);
    roundcp_k<<<256, 256>>>(down_w,     w_down, 393216);

    rmsnorm_k<<<TOK, 128>>>(x, rms1_w, h);
    tgemm_k<0,1><<<dim3(12, 64), 256, SMEM_BYTES>>>(h, DM, w_inp, 2 * DI, xz, 2 * DI,
                                                    TOK, 2 * DI, DM, nullptr, nullptr);
    tconv_k<<<dim3(6, 64), 256, SMEM_BYTES>>>(xz, w_conv, conv_b, xc, xct);
    tgemm_k<0,0><<<dim3(1, 64), 256, SMEM_BYTES>>>(xct, DI, w_xp, 32, bc, 32,
                                                   TOK, 32, DI, nullptr, nullptr);
    tgemm_k<3,0><<<dim3(6, 64), 256, SMEM_BYTES>>>(xct, DI, w_dt, DI, de, DI,
                                                   TOK, DI, DI, dt_proj_b, nullptr);
    scan_k<<<(4 * DI) / 8, 128>>>(xc, de, bc, xz, A_log, D_param, y);
    tgemm_k<0,0><<<dim3(3, 64), 256, SMEM_BYTES>>>(y, DI, w_out, DM, mm, DM,
                                                   TOK, DM, DI, nullptr, nullptr);
    lnres_k<<<TOK, 128>>>(mm, x, ln_gamma, ln_beta, x1);
    rmsnorm_k<<<TOK, 128>>>(x1, rms2_w, h);
    tgemm_k<0,0><<<dim3(8, 64), 256, SMEM_BYTES>>>(h, DM, w_gate, FFNDIM, ga, FFNDIM,
                                                   TOK, FFNDIM, DM, nullptr, nullptr);
    tgemm_k<0,0><<<dim3(8, 64), 256, SMEM_BYTES>>>(h, DM, w_up, FFNDIM, up, FFNDIM,
                                                   TOK, FFNDIM, DM, nullptr, nullptr);
    swiglu_k<<<(TOK * FFNDIM + 255) / 256, 256>>>(ga, up, TOK * FFNDIM);
    tgemm_k<4,0><<<dim3(3, 64), 256, SMEM_BYTES>>>(ga, FFNDIM, w_down, DM, out, DM,
                                                   TOK, DM, FFNDIM, nullptr, x1);
}

// round 7
// speedup vs baseline: 1.5599x; 1.0229x over previous
#include <cuda_runtime.h>
#include <math.h>
#include <stdint.h>

#define TOK   8192
#define DM    384
#define DI    768
#define NST   16
#define FFN   1024
#define LSEQ  2048

#define PADA 20
#define PADB 136
#define STG_WORDS (128 * PADA + 16 * PADB)   // 4736 words / stage
#define NSTG 5
#define SMEM_BYTES (NSTG * STG_WORDS * 4)    // 94720 B

// ---------------- scratch ----------------
__device__ float g_h[TOK * DM];
__device__ float g_xz[TOK * 1536];
__device__ float g_xc[TOK * DI];       // fp32 (scan)
__device__ float g_xct[TOK * DI];      // tf32-rounded (GEMM A)
__device__ float g_dl[TOK * DI];
__device__ float g_bc[TOK * 32];
__device__ float g_y[TOK * DI];
__device__ float g_mm[TOK * DM];
__device__ float g_x1[TOK * DM];
__device__ float g_gu[TOK * 2048];
__device__ float g_ha[TOK * FFN];
// prepared (tf32-rounded, packed) weights
__device__ float w_in[384 * 1536];
__device__ float w_cv[3072 * 768];
__device__ float w_xd[768 * 896];      // cols: 0-31 x_proj, 32-799 dt_proj, 800+ zero
__device__ float w_o[768 * 384];
__device__ float w_gu[384 * 2048];     // cols: 0-1023 gate, 1024-2047 up
__device__ float w_dn[1024 * 384];

__device__ __forceinline__ float siluf(float x) { return x / (1.f + __expf(-x)); }
__device__ __forceinline__ uint32_t f2tf(float f) {
    uint32_t r;
    asm("cvt.rna.tf32.f32 %0, %1;" : "=r"(r) : "f"(f));
    return r;
}
__device__ __forceinline__ float rndtf(float f) { return __uint_as_float(f2tf(f)); }
__device__ __forceinline__ uint32_t sm_u32(const void* p) {
    return (uint32_t)__cvta_generic_to_shared(p);
}
#define CP16(dst, src, sz) \
    asm volatile("cp.async.cg.shared.global [%0], [%1], 16, %2;" :: "r"(dst), "l"(src), "r"(sz))
#define CPCOMMIT() asm volatile("cp.async.commit_group;")
#define CPWAIT3()  asm volatile("cp.async.wait_group 3;")

#define MMA_TF32(d, a, b)                                                    \
    asm volatile(                                                            \
        "mma.sync.aligned.m16n8k8.row.col.f32.tf32.tf32.f32 "                \
        "{%0,%1,%2,%3},{%4,%5,%6,%7},{%8,%9},{%0,%1,%2,%3};\n"               \
        : "+f"((d)[0]), "+f"((d)[1]), "+f"((d)[2]), "+f"((d)[3])             \
        : "r"((a)[0]), "r"((a)[1]), "r"((a)[2]), "r"((a)[3]),                \
          "r"((b)[0]), "r"((b)[1]))

// ---------------- one fused weight-prep kernel ----------------
__global__ void prep_k(const float* __restrict__ inp, const float* __restrict__ cv,
                       const float* __restrict__ xp, const float* __restrict__ dt,
                       const float* __restrict__ op, const float* __restrict__ ga,
                       const float* __restrict__ up, const float* __restrict__ dn) {
    const int TOTAL = 589824 + 2359296 + 688128 + 294912 + 786432 + 393216;
    for (int i = blockIdx.x * blockDim.x + threadIdx.x; i < TOTAL;
         i += gridDim.x * blockDim.x) {
        int j = i;
        float v; float* dst;
        if (j < 589824) { v = inp[j]; dst = &w_in[j]; }
        else if ((j -= 589824) < 2359296) { v = cv[j]; dst = &w_cv[j]; }
        else if ((j -= 2359296) < 688128) {
            int k = j / 896, c = j - k * 896;
            v = (c < 32) ? xp[k * 32 + c] : ((c < 800) ? dt[k * 768 + (c - 32)] : 0.f);
            dst = &w_xd[j];
        }
        else if ((j -= 688128) < 294912) { v = op[j]; dst = &w_o[j]; }
        else if ((j -= 294912) < 786432) {
            int k = j >> 11, c = j & 2047;
            v = (c < 1024) ? ga[k * 1024 + c] : up[k * 1024 + (c - 1024)];
            dst = &w_gu[j];
        }
        else { j -= 786432; v = dn[j]; dst = &w_dn[j]; }
        *dst = rndtf(v);
    }
}

__global__ void dummy_k() {}

// ---------------- RMSNorm (tf32-rounded out) ----------------
__global__ void rmsnorm_k(const float* __restrict__ x, const float* __restrict__ w,
                          float* __restrict__ o) {
    int t = blockIdx.x, tid = threadIdx.x;
    const float* xr = x + (size_t)t * DM;
    float v0 = xr[tid], v1 = xr[tid + 128], v2 = xr[tid + 256];
    float ss = v0 * v0 + v1 * v1 + v2 * v2;
    #pragma unroll
    for (int s = 16; s > 0; s >>= 1) ss += __shfl_xor_sync(0xffffffffu, ss, s);
    __shared__ float sm[4];
    if ((tid & 31) == 0) sm[tid >> 5] = ss;
    __syncthreads();
    float sc = rsqrtf((sm[0] + sm[1] + sm[2] + sm[3]) / (float)DM + 1e-6f);
    float* orow = o + (size_t)t * DM;
    orow[tid]       = rndtf(v0 * sc * w[tid]);
    orow[tid + 128] = rndtf(v1 * sc * w[tid + 128]);
    orow[tid + 256] = rndtf(v2 * sc * w[tid + 256]);
}

// ------------- LayerNorm + residual -------------
__global__ void lnres_k(const float* __restrict__ mm, const float* __restrict__ res,
                        const float* __restrict__ gamma, const float* __restrict__ beta,
                        float* __restrict__ o) {
    int t = blockIdx.x, tid = threadIdx.x;
    const float* r_ = mm + (size_t)t * DM;
    float v0 = r_[tid], v1 = r_[tid + 128], v2 = r_[tid + 256];
    float s = v0 + v1 + v2, ss = v0 * v0 + v1 * v1 + v2 * v2;
    #pragma unroll
    for (int k = 16; k > 0; k >>= 1) {
        s  += __shfl_xor_sync(0xffffffffu, s, k);
        ss += __shfl_xor_sync(0xffffffffu, ss, k);
    }
    __shared__ float sm1[4], sm2[4];
    if ((tid & 31) == 0) { sm1[tid >> 5] = s; sm2[tid >> 5] = ss; }
    __syncthreads();
    s = sm1[0] + sm1[1] + sm1[2] + sm1[3];
    ss = sm2[0] + sm2[1] + sm2[2] + sm2[3];
    float mu = s / (float)DM, var = ss / (float)DM - mu * mu;
    float rs = rsqrtf(var + 1e-5f);
    const float* rr = res + (size_t)t * DM;
    float* orow = o + (size_t)t * DM;
    orow[tid]       = rr[tid]       + (v0 - mu) * rs * gamma[tid]       + beta[tid];
    orow[tid + 128] = rr[tid + 128] + (v1 - mu) * rs * gamma[tid + 128] + beta[tid + 128];
    orow[tid + 256] = rr[tid + 256] + (v2 - mu) * rs * gamma[tid + 256] + beta[tid + 256];
}

// --------- MMA compute on one 16-k tile ---------
__device__ __forceinline__ void mma_tile(const uint32_t* As, const uint32_t* Bs,
                                         int wm, int wn, int lr, int lc,
                                         float acc[4][4][4]) {
    #pragma unroll
    for (int ks = 0; ks < 2; ks++) {
        uint32_t af[4][4], bf[4][2];
        #pragma unroll
        for (int mt = 0; mt < 4; mt++) {
            int R = wm * 64 + mt * 16;
            af[mt][0] = As[(R + lr) * PADA + ks * 8 + lc];
            af[mt][1] = As[(R + lr + 8) * PADA + ks * 8 + lc];
            af[mt][2] = As[(R + lr) * PADA + ks * 8 + 4 + lc];
            af[mt][3] = As[(R + lr + 8) * PADA + ks * 8 + 4 + lc];
        }
        #pragma unroll
        for (int nt = 0; nt < 4; nt++) {
            int CB = wn * 32 + nt * 8;
            bf[nt][0] = Bs[(ks * 8 + lc) * PADB + CB + lr];
            bf[nt][1] = Bs[(ks * 8 + 4 + lc) * PADB + CB + lr];
        }
        #pragma unroll
        for (int mt = 0; mt < 4; mt++)
            #pragma unroll
            for (int nt = 0; nt < 4; nt++) MMA_TF32(acc[mt][nt], af[mt], bf[nt]);
    }
}

// ---------------- 5-stage pipelined TF32 GEMM ----------------
// EPI: 0 = store (RND optional), 2 = fused x_proj|dt_proj epilogue, 4 = +res
template <int EPI, int RND>
__global__ void __launch_bounds__(256, 2) tgemm_k(
    const float* __restrict__ A, int lda,
    const float* __restrict__ B, int ldb,
    float* __restrict__ C, int ldc,
    int M, int N, int K,
    const float* __restrict__ bias,
    const float* __restrict__ res,
    float* __restrict__ O2) {
    extern __shared__ uint32_t sh[];
    int tid = threadIdx.x, lane = tid & 31, wid = tid >> 5;
    int wm = wid >> 2, wn = wid & 3;
    int m0 = blockIdx.y * 128, n0 = blockIdx.x * 128;
    float acc[4][4][4] = {};
    int ar = tid >> 1, ak = (tid & 1) * 8;
    int bk = tid >> 5, bn = (tid & 31) * 4;
    int lr = lane >> 2, lc = lane & 3;

    const float* abase = A + (size_t)(m0 + ar) * lda + ak;
    int bcol = n0 + bn;

    auto load_tile = [&](int st, int k0) {
        uint32_t* As = sh + st * STG_WORDS;
        uint32_t* Bs = As + 128 * PADA;
        const float* ap = abase + k0;
        CP16(sm_u32(&As[ar * PADA + ak]), ap, 16u);
        CP16(sm_u32(&As[ar * PADA + ak + 4]), ap + 4, 16u);
        CP16(sm_u32(&Bs[bk * PADB + bn]), B + (size_t)(k0 + bk) * ldb + bcol, 16u);
        CP16(sm_u32(&Bs[(bk + 8) * PADB + bn]), B + (size_t)(k0 + bk + 8) * ldb + bcol, 16u);
    };

    int KT = K / 16;
    #pragma unroll
    for (int s = 0; s < 4; s++) { load_tile(s, s * 16); CPCOMMIT(); }
    for (int it = 0; it < KT; it++) {
        CPWAIT3();
        __syncthreads();
        int pre = it + 4;
        if (pre < KT) load_tile(pre % NSTG, pre * 16);
        CPCOMMIT();
        const uint32_t* As = sh + (it % NSTG) * STG_WORDS;
        mma_tile(As, As + 128 * PADA, wm, wn, lr, lc, acc);
    }

    int c2 = lc * 2;
    #pragma unroll
    for (int mt = 0; mt < 4; mt++) {
        int row0 = m0 + wm * 64 + mt * 16 + lr;
        #pragma unroll
        for (int nt = 0; nt < 4; nt++) {
            int col = n0 + wn * 32 + nt * 8 + c2;
            #pragma unroll
            for (int h = 0; h < 2; h++) {
                int row = row0 + h * 8;
                float e0 = acc[mt][nt][h * 2 + 0];
                float e1 = acc[mt][nt][h * 2 + 1];
                if (EPI == 2) {
                    #pragma unroll
                    for (int jj = 0; jj < 2; jj++) {
                        int c = col + jj;
                        float e = (jj == 0) ? e0 : e1;
                        if (c < 32) {
                            C[(size_t)row * 32 + c] = e;
                        } else if (c < 800) {
                            float tv = e + bias[c - 32];
                            O2[(size_t)row * DI + (c - 32)] =
                                (tv > 20.f) ? tv : log1pf(__expf(tv));
                        }
                    }
                } else {
                    if (EPI == 4) {
                        e0 += res[(size_t)row * ldc + col];
                        e1 += res[(size_t)row * ldc + col + 1];
                    }
                    if (RND) { e0 = rndtf(e0); e1 = rndtf(e1); }
                    *(float2*)(C + (size_t)row * ldc + col) = make_float2(e0, e1);
                }
            }
        }
    }
}

// -------- conv1d (k=4, SAME (1,2)) implicit-im2col, 5-stage --------
__global__ void __launch_bounds__(256, 2) tconv_k(
    const float* __restrict__ xz, const float* __restrict__ W,
    const float* __restrict__ bias, float* __restrict__ outf,
    float* __restrict__ outt) {
    extern __shared__ uint32_t sh[];
    int tid = threadIdx.x, lane = tid & 31, wid = tid >> 5;
    int wm = wid >> 2, wn = wid & 3;
    int m0 = blockIdx.y * 128, n0 = blockIdx.x * 128;
    float acc[4][4][4] = {};
    int ar = tid >> 1, ak = (tid & 1) * 8;
    int bk = tid >> 5, bn = (tid & 31) * 4;
    int lr = lane >> 2, lc = lane & 3;

    int tok = m0 + ar;
    int l = tok & (LSEQ - 1);
    int tb = tok - l;

    auto load_tile = [&](int st, int kk) {
        int w = kk / 48;
        int k0 = (kk - w * 48) * 16;
        uint32_t* As = sh + st * STG_WORDS;
        uint32_t* Bs = As + 128 * PADA;
        int ls = l + w - 1;
        uint32_t asz = ((unsigned)ls < LSEQ) ? 16u : 0u;
        int lss = asz ? ls : 0;
        const float* ap = xz + (size_t)(tb + lss) * 1536 + k0 + ak;
        CP16(sm_u32(&As[ar * PADA + ak]), ap, asz);
        CP16(sm_u32(&As[ar * PADA + ak + 4]), ap + 4, asz);
        const float* bp = W + (size_t)(w * DI + k0 + bk) * DI + n0 + bn;
        CP16(sm_u32(&Bs[bk * PADB + bn]), bp, 16u);
        CP16(sm_u32(&Bs[(bk + 8) * PADB + bn]), bp + 8 * DI, 16u);
    };

    const int KT = 192;
    #pragma unroll
    for (int s = 0; s < 4; s++) { load_tile(s, s); CPCOMMIT(); }
    for (int it = 0; it < KT; it++) {
        CPWAIT3();
        __syncthreads();
        int pre = it + 4;
        if (pre < KT) load_tile(pre % NSTG, pre);
        CPCOMMIT();
        const uint32_t* As = sh + (it % NSTG) * STG_WORDS;
        mma_tile(As, As + 128 * PADA, wm, wn, lr, lc, acc);
    }

    int c2 = lc * 2;
    #pragma unroll
    for (int mt = 0; mt < 4; mt++) {
        int row0 = m0 + wm * 64 + mt * 16 + lr;
        #pragma unroll
        for (int nt = 0; nt < 4; nt++) {
            int col = n0 + wn * 32 + nt * 8 + c2;
            #pragma unroll
            for (int h = 0; h < 2; h++) {
                int row = row0 + h * 8;
                float e0 = siluf(acc[mt][nt][h * 2 + 0] + bias[col]);
                float e1 = siluf(acc[mt][nt][h * 2 + 1] + bias[col + 1]);
                *(float2*)(outf + (size_t)row * DI + col) = make_float2(e0, e1);
                *(float2*)(outt + (size_t)row * DI + col) =
                    make_float2(rndtf(e0), rndtf(e1));
            }
        }
    }
}

// ---------------- selective scan ----------------
__global__ void scan_k(const float* __restrict__ xc, const float* __restrict__ dl,
                       const float* __restrict__ bc, const float* __restrict__ xz,
                       const float* __restrict__ A_log, const float* __restrict__ Dp,
                       float* __restrict__ y) {
    int tid = threadIdx.x;
    int pair = blockIdx.x * 8 + (tid >> 4);
    int n = tid & 15;
    int b = pair / DI, d = pair - b * DI;
    float a = -__expf(A_log[d * NST + n]);
    float Dv = Dp[d];
    float hs = 0.f;
    size_t base = (size_t)b * LSEQ;
    #pragma unroll 4
    for (int l = 0; l < LSEQ; l++) {
        size_t t = base + l;
        float xv = xc[t * DI + d];
        float de = dl[t * DI + d];
        float Bv = bc[t * 32 + n];
        float Cv = bc[t * 32 + 16 + n];
        hs = __expf(de * a) * hs + de * Bv * xv;
        float yv = hs * Cv;
        yv += __shfl_xor_sync(0xffffffffu, yv, 8);
        yv += __shfl_xor_sync(0xffffffffu, yv, 4);
        yv += __shfl_xor_sync(0xffffffffu, yv, 2);
        yv += __shfl_xor_sync(0xffffffffu, yv, 1);
        if (n == 0) {
            float z = xz[t * 1536 + DI + d];
            y[t * DI + d] = rndtf((yv + Dv * xv) * siluf(z));
        }
    }
}

// ---------------- SwiGLU (reads fused gu buffer) ----------------
__global__ void swiglu_k(const float* __restrict__ gu, float* __restrict__ o) {
    int i = blockIdx.x * blockDim.x + threadIdx.x;
    if (i < TOK * FFN) {
        int t = i >> 10, c = i & 1023;
        float g = gu[(size_t)t * 2048 + c];
        float u = gu[(size_t)t * 2048 + 1024 + c];
        o[i] = rndtf(siluf(g) * u);
    }
}

// ---------------- launch ----------------
extern "C" void kernel_launch(void* const* d_in, const int* in_sizes, int n_in,
                              void* d_out, int out_size) {
    const float* x         = (const float*)d_in[0];
    const float* rms1_w    = (const float*)d_in[1];
    const float* rms2_w    = (const float*)d_in[2];
    const float* in_proj_w = (const float*)d_in[3];
    const float* conv_w    = (const float*)d_in[4];
    const float* conv_b    = (const float*)d_in[5];
    const float* x_proj_w  = (const float*)d_in[6];
    const float* dt_proj_w = (const float*)d_in[7];
    const float* dt_proj_b = (const float*)d_in[8];
    const float* A_log     = (const float*)d_in[9];
    const float* D_param   = (const float*)d_in[10];
    const float* out_proj_w= (const float*)d_in[11];
    const float* ln_gamma  = (const float*)d_in[12];
    const float* ln_beta   = (const float*)d_in[13];
    const float* gate_w    = (const float*)d_in[14];
    const float* up_w      = (const float*)d_in[15];
    const float* down_w    = (const float*)d_in[16];
    float* out = (float*)d_out;

    float *h, *xz, *xc, *xct, *dl, *bc, *y, *mm, *x1, *gu, *ha;
    float *pwin, *pwcv, *pwxd, *pwo, *pwgu, *pwdn;
    cudaGetSymbolAddress((void**)&h,   g_h);
    cudaGetSymbolAddress((void**)&xz,  g_xz);
    cudaGetSymbolAddress((void**)&xc,  g_xc);
    cudaGetSymbolAddress((void**)&xct, g_xct);
    cudaGetSymbolAddress((void**)&dl,  g_dl);
    cudaGetSymbolAddress((void**)&bc,  g_bc);
    cudaGetSymbolAddress((void**)&y,   g_y);
    cudaGetSymbolAddress((void**)&mm,  g_mm);
    cudaGetSymbolAddress((void**)&x1,  g_x1);
    cudaGetSymbolAddress((void**)&gu,  g_gu);
    cudaGetSymbolAddress((void**)&ha,  g_ha);
    cudaGetSymbolAddress((void**)&pwin, w_in);
    cudaGetSymbolAddress((void**)&pwcv, w_cv);
    cudaGetSymbolAddress((void**)&pwxd, w_xd);
    cudaGetSymbolAddress((void**)&pwo,  w_o);
    cudaGetSymbolAddress((void**)&pwgu, w_gu);
    cudaGetSymbolAddress((void**)&pwdn, w_dn);

    cudaFuncSetAttribute(tgemm_k<0,1>, cudaFuncAttributeMaxDynamicSharedMemorySize, SMEM_BYTES);
    cudaFuncSetAttribute(tgemm_k<0,0>, cudaFuncAttributeMaxDynamicSharedMemorySize, SMEM_BYTES);
    cudaFuncSetAttribute(tgemm_k<2,0>, cudaFuncAttributeMaxDynamicSharedMemorySize, SMEM_BYTES);
    cudaFuncSetAttribute(tgemm_k<4,0>, cudaFuncAttributeMaxDynamicSharedMemorySize, SMEM_BYTES);
    cudaFuncSetAttribute(tconv_k,      cudaFuncAttributeMaxDynamicSharedMemorySize, SMEM_BYTES);

    // #0 prep (single launch)
    prep_k<<<512, 256>>>(in_proj_w, conv_w, x_proj_w, dt_proj_w,
                         out_proj_w, gate_w, up_w, down_w);
    // #1 rms1
    rmsnorm_k<<<TOK, 128>>>(x, rms1_w, h);
    // #2 in_proj [8192,384]@[384,1536] -> xz (rounded fp32)
    tgemm_k<0,1><<<dim3(12, 64), 256, SMEM_BYTES>>>(h, DM, pwin, 1536, xz, 1536,
        TOK, 1536, DM, nullptr, nullptr, nullptr);
    // #3,#4 dummies so ncu (-s 5) captures the conv GEMM
    dummy_k<<<1, 1>>>();
    dummy_k<<<1, 1>>>();
    // #5 conv (im2col GEMM, K_eff=3072)
    tconv_k<<<dim3(6, 64), 256, SMEM_BYTES>>>(xz, pwcv, conv_b, xc, xct);
    // #6 fused x_proj + dt_proj: [8192,768]@[768,896]
    tgemm_k<2,0><<<dim3(7, 64), 256, SMEM_BYTES>>>(xct, DI, pwxd, 896, bc, 32,
        TOK, 896, DI, dt_proj_b, nullptr, dl);
    // #7 scan
    scan_k<<<(4 * DI) / 8, 128>>>(xc, dl, bc, xz, A_log, D_param, y);
    // #8 out_proj
    tgemm_k<0,0><<<dim3(3, 64), 256, SMEM_BYTES>>>(y, DI, pwo, DM, mm, DM,
        TOK, DM, DI, nullptr, nullptr, nullptr);
    // #9 layernorm + residual
    lnres_k<<<TOK, 128>>>(mm, x, ln_gamma, ln_beta, x1);
    // #10 rms2
    rmsnorm_k<<<TOK, 128>>>(x1, rms2_w, h);
    // #11 fused gate+up: [8192,384]@[384,2048]
    tgemm_k<0,0><<<dim3(16, 64), 256, SMEM_BYTES>>>(h, DM, pwgu, 2048, gu, 2048,
        TOK, 2048, DM, nullptr, nullptr, nullptr);
    // #12 swiglu
    swiglu_k<<<(TOK * FFN + 255) / 256, 256>>>(gu, ha);
    // #13 down + residual
    tgemm_k<4,0><<<dim3(3, 64), 256, SMEM_BYTES>>>(ha, FFN, pwdn, DM, out, DM,
        TOK, DM, FFN, nullptr, x1, nullptr);
}

// round 8
// speedup vs baseline: 1.8856x; 1.2088x over previous
#include <cuda_runtime.h>
#include <cuda_fp16.h>
#include <math.h>
#include <stdint.h>

#define TOK   8192
#define DM    384
#define DI    768
#define NST   16
#define FFN   1024
#define LSEQ  2048

#define STG_WORDS 5120                 // A 128x20 + B 128x20 words per stage
#define NSTG 5
#define SMEM_BYTES (NSTG * STG_WORDS * 4)   // 102400 B

// ---------------- scratch ----------------
__device__ __half g_hh[TOK * DM];
__device__ __half g_xzh[TOK * 1536];
__device__ __half g_xch[TOK * DI];
__device__ float  g_xc[TOK * DI];
__device__ float  g_dl[TOK * DI];
__device__ float  g_bc[TOK * 32];
__device__ __half g_yh[TOK * DI];
__device__ float  g_mm[TOK * DM];
__device__ float  g_x1[TOK * DM];
__device__ __half g_guh[TOK * 2048];
__device__ __half g_hah[TOK * FFN];
// transposed fp16 weights [N][K] (K contiguous)
__device__ __half w_in[1536 * 384];
__device__ __half w_cv[768 * 3072];
__device__ __half w_xd[896 * 768];   // rows: 0-31 x_proj, 32-799 dt_proj, 800-895 zero
__device__ __half w_o [384 * 768];
__device__ __half w_gu[2048 * 384];  // rows: 0-1023 gate, 1024-2047 up
__device__ __half w_dn[384 * 1024];

__device__ __forceinline__ float siluf(float x) { return x / (1.f + __expf(-x)); }
__device__ __forceinline__ uint32_t sm_u32(const void* p) {
    return (uint32_t)__cvta_generic_to_shared(p);
}
#define CP16(dst, src, sz) \
    asm volatile("cp.async.cg.shared.global [%0], [%1], 16, %2;" :: "r"(dst), "l"(src), "r"(sz))
#define CPCOMMIT() asm volatile("cp.async.commit_group;")
#define CPWAIT3()  asm volatile("cp.async.wait_group 3;")

#define MMA_F16(d, a, b)                                                     \
    asm volatile(                                                            \
        "mma.sync.aligned.m16n8k16.row.col.f32.f16.f16.f32 "                 \
        "{%0,%1,%2,%3},{%4,%5,%6,%7},{%8,%9},{%0,%1,%2,%3};\n"               \
        : "+f"((d)[0]), "+f"((d)[1]), "+f"((d)[2]), "+f"((d)[3])             \
        : "r"((a)[0]), "r"((a)[1]), "r"((a)[2]), "r"((a)[3]),                \
          "r"((b)[0]), "r"((b)[1]))

// ---------------- single prep kernel: transpose + fp16-convert all weights ---------
__global__ void prep_k(const float* __restrict__ inp, const float* __restrict__ cv,
                       const float* __restrict__ xp, const float* __restrict__ dt,
                       const float* __restrict__ op, const float* __restrict__ ga,
                       const float* __restrict__ up, const float* __restrict__ dn) {
    int sel = blockIdx.z;
    int K_, N_; __half* dst;
    switch (sel) {
        case 0: K_ = 384;  N_ = 1536; dst = w_in; break;
        case 1: K_ = 3072; N_ = 768;  dst = w_cv; break;
        case 2: K_ = 768;  N_ = 896;  dst = w_xd; break;
        case 3: K_ = 768;  N_ = 384;  dst = w_o;  break;
        case 4: K_ = 384;  N_ = 2048; dst = w_gu; break;
        default:K_ = 1024; N_ = 384;  dst = w_dn; break;
    }
    int k0 = blockIdx.x * 32, n0 = blockIdx.y * 32;
    if (k0 >= K_ || n0 >= N_) return;
    __shared__ float t[32][33];
    int tx = threadIdx.x, ty = threadIdx.y;
    for (int i = ty; i < 32; i += 8) {
        int k = k0 + i, n = n0 + tx;
        float v = 0.f;
        if (k < K_ && n < N_) {
            switch (sel) {
                case 0: v = inp[(size_t)k * 1536 + n]; break;
                case 1: v = cv[(size_t)k * 768 + n]; break;
                case 2: v = (n < 32) ? xp[(size_t)k * 32 + n]
                          : (n < 800 ? dt[(size_t)k * 768 + (n - 32)] : 0.f); break;
                case 3: v = op[(size_t)k * 384 + n]; break;
                case 4: v = (n < 1024) ? ga[(size_t)k * 1024 + n]
                                       : up[(size_t)k * 1024 + (n - 1024)]; break;
                default: v = dn[(size_t)k * 384 + n]; break;
            }
        }
        t[i][tx] = v;
    }
    __syncthreads();
    for (int i = ty; i < 32; i += 8) {
        int n = n0 + i, k = k0 + tx;
        if (n < N_ && k < K_) dst[(size_t)n * K_ + k] = __float2half(t[tx][i]);
    }
}

__global__ void dummy_k() {}

// ---------------- RMSNorm -> fp16 ----------------
__global__ void rmsnorm_k(const float* __restrict__ x, const float* __restrict__ w,
                          __half* __restrict__ o) {
    int t = blockIdx.x, tid = threadIdx.x;
    const float* xr = x + (size_t)t * DM;
    float v0 = xr[tid], v1 = xr[tid + 128], v2 = xr[tid + 256];
    float ss = v0 * v0 + v1 * v1 + v2 * v2;
    #pragma unroll
    for (int s = 16; s > 0; s >>= 1) ss += __shfl_xor_sync(0xffffffffu, ss, s);
    __shared__ float sm[4];
    if ((tid & 31) == 0) sm[tid >> 5] = ss;
    __syncthreads();
    float sc = rsqrtf((sm[0] + sm[1] + sm[2] + sm[3]) / (float)DM + 1e-6f);
    __half* orow = o + (size_t)t * DM;
    orow[tid]       = __float2half(v0 * sc * w[tid]);
    orow[tid + 128] = __float2half(v1 * sc * w[tid + 128]);
    orow[tid + 256] = __float2half(v2 * sc * w[tid + 256]);
}

// ------------- LayerNorm + residual (fp32) -------------
__global__ void lnres_k(const float* __restrict__ mm, const float* __restrict__ res,
                        const float* __restrict__ gamma, const float* __restrict__ beta,
                        float* __restrict__ o) {
    int t = blockIdx.x, tid = threadIdx.x;
    const float* r_ = mm + (size_t)t * DM;
    float v0 = r_[tid], v1 = r_[tid + 128], v2 = r_[tid + 256];
    float s = v0 + v1 + v2, ss = v0 * v0 + v1 * v1 + v2 * v2;
    #pragma unroll
    for (int k = 16; k > 0; k >>= 1) {
        s  += __shfl_xor_sync(0xffffffffu, s, k);
        ss += __shfl_xor_sync(0xffffffffu, ss, k);
    }
    __shared__ float sm1[4], sm2[4];
    if ((tid & 31) == 0) { sm1[tid >> 5] = s; sm2[tid >> 5] = ss; }
    __syncthreads();
    s = sm1[0] + sm1[1] + sm1[2] + sm1[3];
    ss = sm2[0] + sm2[1] + sm2[2] + sm2[3];
    float mu = s / (float)DM, var = ss / (float)DM - mu * mu;
    float rs = rsqrtf(var + 1e-5f);
    const float* rr = res + (size_t)t * DM;
    float* orow = o + (size_t)t * DM;
    orow[tid]       = rr[tid]       + (v0 - mu) * rs * gamma[tid]       + beta[tid];
    orow[tid + 128] = rr[tid + 128] + (v1 - mu) * rs * gamma[tid + 128] + beta[tid + 128];
    orow[tid + 256] = rr[tid + 256] + (v2 - mu) * rs * gamma[tid + 256] + beta[tid + 256];
}

// --------- fp16 MMA on one 32-k tile (2 slabs of k16) ---------
__device__ __forceinline__ void mma_tile16(const uint32_t* As, const uint32_t* Bs,
                                           int wm, int wn, int lr, int lc,
                                           float acc[4][4][4]) {
    #pragma unroll
    for (int sl = 0; sl < 2; sl++) {
        int w0 = sl * 8 + lc;
        uint32_t af[4][4], bf[4][2];
        #pragma unroll
        for (int mt = 0; mt < 4; mt++) {
            int R = wm * 64 + mt * 16;
            af[mt][0] = As[(R + lr) * 20 + w0];
            af[mt][1] = As[(R + lr + 8) * 20 + w0];
            af[mt][2] = As[(R + lr) * 20 + w0 + 4];
            af[mt][3] = As[(R + lr + 8) * 20 + w0 + 4];
        }
        #pragma unroll
        for (int nt = 0; nt < 4; nt++) {
            int CB = wn * 32 + nt * 8;
            bf[nt][0] = Bs[(CB + lr) * 20 + w0];
            bf[nt][1] = Bs[(CB + lr) * 20 + w0 + 4];
        }
        #pragma unroll
        for (int mt = 0; mt < 4; mt++)
            #pragma unroll
            for (int nt = 0; nt < 4; nt++) MMA_F16(acc[mt][nt], af[mt], bf[nt]);
    }
}

// ---------------- fp16 5-stage pipelined GEMM ----------------
// A [M][K] fp16 row-major, B [N][K] fp16 (K contiguous). BM=BN=128, BK=32.
// EPI: 0 = store fp16, 2 = fused x_proj|dt_proj, 3 = store fp32, 4 = +res fp32
template <int EPI>
__global__ void __launch_bounds__(256, 2) hgemm_k(
    const __half* __restrict__ A, int lda,
    const __half* __restrict__ B, int ldb,
    int KT,
    float* __restrict__ Cf, __half* __restrict__ Ch, int ldc,
    const float* __restrict__ bias, const float* __restrict__ res,
    float* __restrict__ O2) {
    extern __shared__ uint32_t sh[];
    int tid = threadIdx.x, lane = tid & 31, wid = tid >> 5;
    int wm = wid >> 2, wn = wid & 3;
    int m0 = blockIdx.y * 128, n0 = blockIdx.x * 128;
    float acc[4][4][4] = {};
    int lr = lane >> 2, lc = lane & 3;
    int arow = tid >> 1, ahalf = (tid & 1) * 16;

    const __half* abase = A + (size_t)(m0 + arow) * lda + ahalf;
    const __half* bbase = B + (size_t)(n0 + arow) * ldb + ahalf;

    auto load_stage = [&](int st, int k0) {
        uint32_t sb = sm_u32(sh) + st * (STG_WORDS * 4);
        uint32_t da = sb + (arow * 40 + ahalf) * 2;
        uint32_t db = sb + 10240 + (arow * 40 + ahalf) * 2;
        CP16(da,      abase + k0, 16u);
        CP16(da + 16, abase + k0 + 8, 16u);
        CP16(db,      bbase + k0, 16u);
        CP16(db + 16, bbase + k0 + 8, 16u);
    };

    #pragma unroll
    for (int s = 0; s < 4; s++) { load_stage(s, s * 32); CPCOMMIT(); }
    for (int it = 0; it < KT; it++) {
        CPWAIT3();
        __syncthreads();
        int pre = it + 4;
        if (pre < KT) load_stage(pre % NSTG, pre * 32);
        CPCOMMIT();
        const uint32_t* As = sh + (it % NSTG) * STG_WORDS;
        mma_tile16(As, As + 2560, wm, wn, lr, lc, acc);
    }

    int c2 = lc * 2;
    #pragma unroll
    for (int mt = 0; mt < 4; mt++) {
        int row0 = m0 + wm * 64 + mt * 16 + lr;
        #pragma unroll
        for (int nt = 0; nt < 4; nt++) {
            int col = n0 + wn * 32 + nt * 8 + c2;
            #pragma unroll
            for (int h = 0; h < 2; h++) {
                int row = row0 + h * 8;
                float e0 = acc[mt][nt][h * 2 + 0];
                float e1 = acc[mt][nt][h * 2 + 1];
                if (EPI == 0) {
                    *(__half2*)(Ch + (size_t)row * ldc + col) =
                        __floats2half2_rn(e0, e1);
                } else if (EPI == 2) {
                    #pragma unroll
                    for (int jj = 0; jj < 2; jj++) {
                        int c = col + jj;
                        float e = (jj == 0) ? e0 : e1;
                        if (c < 32) {
                            Cf[(size_t)row * 32 + c] = e;
                        } else if (c < 800) {
                            float tv = e + bias[c - 32];
                            O2[(size_t)row * DI + (c - 32)] =
                                (tv > 20.f) ? tv : log1pf(__expf(tv));
                        }
                    }
                } else {
                    if (EPI == 4) {
                        e0 += res[(size_t)row * ldc + col];
                        e1 += res[(size_t)row * ldc + col + 1];
                    }
                    *(float2*)(Cf + (size_t)row * ldc + col) = make_float2(e0, e1);
                }
            }
        }
    }
}

// -------- conv1d (k=4, SAME (1,2)) implicit-im2col fp16 GEMM --------
__global__ void __launch_bounds__(256, 2) hconv_k(
    const __half* __restrict__ xz, const __half* __restrict__ W,
    const float* __restrict__ bias, float* __restrict__ outf,
    __half* __restrict__ outh) {
    extern __shared__ uint32_t sh[];
    int tid = threadIdx.x, lane = tid & 31, wid = tid >> 5;
    int wm = wid >> 2, wn = wid & 3;
    int m0 = blockIdx.y * 128, n0 = blockIdx.x * 128;
    float acc[4][4][4] = {};
    int lr = lane >> 2, lc = lane & 3;
    int arow = tid >> 1, ahalf = (tid & 1) * 16;

    int tok = m0 + arow;
    int l = tok & (LSEQ - 1);
    int tb = tok - l;
    const __half* bbase = W + (size_t)(n0 + arow) * 3072 + ahalf;

    auto load_stage = [&](int st, int it) {
        int w = it / 24;
        int koff = (it - w * 24) * 32;
        int ls = l + w - 1;
        uint32_t asz = ((unsigned)ls < LSEQ) ? 16u : 0u;
        const __half* ap = xz + (size_t)(tb + (asz ? ls : 0)) * 1536 + koff + ahalf;
        uint32_t sb = sm_u32(sh) + st * (STG_WORDS * 4);
        uint32_t da = sb + (arow * 40 + ahalf) * 2;
        uint32_t db = sb + 10240 + (arow * 40 + ahalf) * 2;
        CP16(da,      ap, asz);
        CP16(da + 16, ap + 8, asz);
        const __half* bp = bbase + it * 32;
        CP16(db,      bp, 16u);
        CP16(db + 16, bp + 8, 16u);
    };

    const int KT = 96;
    #pragma unroll
    for (int s = 0; s < 4; s++) { load_stage(s, s); CPCOMMIT(); }
    for (int it = 0; it < KT; it++) {
        CPWAIT3();
        __syncthreads();
        int pre = it + 4;
        if (pre < KT) load_stage(pre % NSTG, pre);
        CPCOMMIT();
        const uint32_t* As = sh + (it % NSTG) * STG_WORDS;
        mma_tile16(As, As + 2560, wm, wn, lr, lc, acc);
    }

    int c2 = lc * 2;
    #pragma unroll
    for (int mt = 0; mt < 4; mt++) {
        int row0 = m0 + wm * 64 + mt * 16 + lr;
        #pragma unroll
        for (int nt = 0; nt < 4; nt++) {
            int col = n0 + wn * 32 + nt * 8 + c2;
            #pragma unroll
            for (int h = 0; h < 2; h++) {
                int row = row0 + h * 8;
                float e0 = siluf(acc[mt][nt][h * 2 + 0] + bias[col]);
                float e1 = siluf(acc[mt][nt][h * 2 + 1] + bias[col + 1]);
                *(float2*)(outf + (size_t)row * DI + col) = make_float2(e0, e1);
                *(__half2*)(outh + (size_t)row * DI + col) = __floats2half2_rn(e0, e1);
            }
        }
    }
}

// ---------------- selective scan ----------------
__global__ void scan_k(const float* __restrict__ xc, const float* __restrict__ dl,
                       const float* __restrict__ bc, const __half* __restrict__ xzh,
                       const float* __restrict__ A_log, const float* __restrict__ Dp,
                       __half* __restrict__ y) {
    int tid = threadIdx.x;
    int pair = blockIdx.x * 8 + (tid >> 4);
    int n = tid & 15;
    int b = pair / DI, d = pair - b * DI;
    float a = -__expf(A_log[d * NST + n]);
    float Dv = Dp[d];
    float hs = 0.f;
    size_t base = (size_t)b * LSEQ;
    #pragma unroll 4
    for (int l = 0; l < LSEQ; l++) {
        size_t t = base + l;
        float xv = xc[t * DI + d];
        float de = dl[t * DI + d];
        float Bv = bc[t * 32 + n];
        float Cv = bc[t * 32 + 16 + n];
        hs = __expf(de * a) * hs + de * Bv * xv;
        float yv = hs * Cv;
        yv += __shfl_xor_sync(0xffffffffu, yv, 8);
        yv += __shfl_xor_sync(0xffffffffu, yv, 4);
        yv += __shfl_xor_sync(0xffffffffu, yv, 2);
        yv += __shfl_xor_sync(0xffffffffu, yv, 1);
        if (n == 0) {
            float z = __half2float(xzh[t * 1536 + DI + d]);
            y[t * DI + d] = __float2half((yv + Dv * xv) * siluf(z));
        }
    }
}

// ---------------- SwiGLU ----------------
__global__ void swiglu_k(const __half* __restrict__ gu, __half* __restrict__ o) {
    int i = blockIdx.x * blockDim.x + threadIdx.x;
    if (i < TOK * FFN) {
        int t = i >> 10, c = i & 1023;
        float g = __half2float(gu[(size_t)t * 2048 + c]);
        float u = __half2float(gu[(size_t)t * 2048 + 1024 + c]);
        o[i] = __float2half(siluf(g) * u);
    }
}

// ---------------- launch ----------------
extern "C" void kernel_launch(void* const* d_in, const int* in_sizes, int n_in,
                              void* d_out, int out_size) {
    const float* x         = (const float*)d_in[0];
    const float* rms1_w    = (const float*)d_in[1];
    const float* rms2_w    = (const float*)d_in[2];
    const float* in_proj_w = (const float*)d_in[3];
    const float* conv_w    = (const float*)d_in[4];
    const float* conv_b    = (const float*)d_in[5];
    const float* x_proj_w  = (const float*)d_in[6];
    const float* dt_proj_w = (const float*)d_in[7];
    const float* dt_proj_b = (const float*)d_in[8];
    const float* A_log     = (const float*)d_in[9];
    const float* D_param   = (const float*)d_in[10];
    const float* out_proj_w= (const float*)d_in[11];
    const float* ln_gamma  = (const float*)d_in[12];
    const float* ln_beta   = (const float*)d_in[13];
    const float* gate_w    = (const float*)d_in[14];
    const float* up_w      = (const float*)d_in[15];
    const float* down_w    = (const float*)d_in[16];
    float* out = (float*)d_out;

    __half *hh, *xzh, *xch, *yh, *guh, *hah;
    __half *pwin, *pwcv, *pwxd, *pwo, *pwgu, *pwdn;
    float *xc, *dl, *bc, *mm, *x1;
    cudaGetSymbolAddress((void**)&hh,  g_hh);
    cudaGetSymbolAddress((void**)&xzh, g_xzh);
    cudaGetSymbolAddress((void**)&xch, g_xch);
    cudaGetSymbolAddress((void**)&xc,  g_xc);
    cudaGetSymbolAddress((void**)&dl,  g_dl);
    cudaGetSymbolAddress((void**)&bc,  g_bc);
    cudaGetSymbolAddress((void**)&yh,  g_yh);
    cudaGetSymbolAddress((void**)&mm,  g_mm);
    cudaGetSymbolAddress((void**)&x1,  g_x1);
    cudaGetSymbolAddress((void**)&guh, g_guh);
    cudaGetSymbolAddress((void**)&hah, g_hah);
    cudaGetSymbolAddress((void**)&pwin, w_in);
    cudaGetSymbolAddress((void**)&pwcv, w_cv);
    cudaGetSymbolAddress((void**)&pwxd, w_xd);
    cudaGetSymbolAddress((void**)&pwo,  w_o);
    cudaGetSymbolAddress((void**)&pwgu, w_gu);
    cudaGetSymbolAddress((void**)&pwdn, w_dn);

    cudaFuncSetAttribute(hgemm_k<0>, cudaFuncAttributeMaxDynamicSharedMemorySize, SMEM_BYTES);
    cudaFuncSetAttribute(hgemm_k<2>, cudaFuncAttributeMaxDynamicSharedMemorySize, SMEM_BYTES);
    cudaFuncSetAttribute(hgemm_k<3>, cudaFuncAttributeMaxDynamicSharedMemorySize, SMEM_BYTES);
    cudaFuncSetAttribute(hgemm_k<4>, cudaFuncAttributeMaxDynamicSharedMemorySize, SMEM_BYTES);
    cudaFuncSetAttribute(hconv_k,    cudaFuncAttributeMaxDynamicSharedMemorySize, SMEM_BYTES);

    // #0 prep (transpose + fp16 all weights, one launch)
    prep_k<<<dim3(96, 64, 6), dim3(32, 8)>>>(in_proj_w, conv_w, x_proj_w, dt_proj_w,
                                             out_proj_w, gate_w, up_w, down_w);
    // #1 rms1 -> fp16
    rmsnorm_k<<<TOK, 128>>>(x, rms1_w, hh);
    // #2 in_proj [8192,384]@[384,1536] -> xz fp16
    hgemm_k<0><<<dim3(12, 64), 256, SMEM_BYTES>>>(hh, DM, pwin, DM, 12,
        nullptr, xzh, 1536, nullptr, nullptr, nullptr);
    // #3 dummy (aligns conv to absolute launch #5 incl. harness poison)
    dummy_k<<<1, 1>>>();
    // #4 conv (im2col GEMM, K_eff=3072)
    hconv_k<<<dim3(6, 64), 256, SMEM_BYTES>>>(xzh, pwcv, conv_b, xc, xch);
    // #5 fused x_proj + dt_proj: [8192,768]@[768,896]
    hgemm_k<2><<<dim3(7, 64), 256, SMEM_BYTES>>>(xch, DI, pwxd, DI, 24,
        bc, nullptr, 32, dt_proj_b, nullptr, dl);
    // #6 scan
    scan_k<<<(4 * DI) / 8, 128>>>(xc, dl, bc, xzh, A_log, D_param, yh);
    // #7 out_proj -> mm fp32
    hgemm_k<3><<<dim3(3, 64), 256, SMEM_BYTES>>>(yh, DI, pwo, DI, 24,
        mm, nullptr, DM, nullptr, nullptr, nullptr);
    // #8 layernorm + residual
    lnres_k<<<TOK, 128>>>(mm, x, ln_gamma, ln_beta, x1);
    // #9 rms2 -> fp16
    rmsnorm_k<<<TOK, 128>>>(x1, rms2_w, hh);
    // #10 fused gate+up: [8192,384]@[384,2048] -> fp16
    hgemm_k<0><<<dim3(16, 64), 256, SMEM_BYTES>>>(hh, DM, pwgu, DM, 12,
        nullptr, guh, 2048, nullptr, nullptr, nullptr);
    // #11 swiglu -> fp16
    swiglu_k<<<(TOK * FFN + 255) / 256, 256>>>(guh, hah);
    // #12 down + residual -> out fp32
    hgemm_k<4><<<dim3(3, 64), 256, SMEM_BYTES>>>(hah, FFN, pwdn, FFN, 32,
        out, nullptr, DM, nullptr, x1, nullptr);
}